// round 4
// baseline (speedup 1.0000x reference)
#include <cuda_runtime.h>
#include <math.h>
#include <stdint.h>

#define H_  16
#define HD_ 64
#define D_  1024
#define B_  2
#define S_  2048
#define MROWS (B_*S_)   // 4096

__device__ float g_q[(size_t)B_*H_*S_*HD_];
__device__ float g_k[(size_t)B_*H_*S_*HD_];
__device__ float g_v[(size_t)B_*H_*S_*HD_];
__device__ float g_att[(size_t)MROWS*D_];

// ---------------------------------------------------------------------------
__device__ __forceinline__ uint32_t f2tf(float f) {
    uint32_t r; asm("cvt.rna.tf32.f32 %0, %1;" : "=r"(r) : "f"(f)); return r;
}
__device__ __forceinline__ float f2tff(float f) { return __uint_as_float(f2tf(f)); }
__device__ __forceinline__ float4 cvt4(float4 v) {
    float4 r; r.x=f2tff(v.x); r.y=f2tff(v.y); r.z=f2tff(v.z); r.w=f2tff(v.w); return r;
}
__device__ __forceinline__ float4 cvt4s(float4 v, float s) {
    float4 r; r.x=f2tff(v.x*s); r.y=f2tff(v.y*s); r.z=f2tff(v.z*s); r.w=f2tff(v.w*s); return r;
}

__device__ __forceinline__ void mma8(float* c,
    uint32_t a0, uint32_t a1, uint32_t a2, uint32_t a3,
    uint32_t b0, uint32_t b1)
{
    asm volatile(
        "mma.sync.aligned.m16n8k8.row.col.f32.tf32.tf32.f32 "
        "{%0,%1,%2,%3}, {%4,%5,%6,%7}, {%8,%9}, {%0,%1,%2,%3};"
        : "+f"(c[0]), "+f"(c[1]), "+f"(c[2]), "+f"(c[3])
        : "r"(a0), "r"(a1), "r"(a2), "r"(a3), "r"(b0), "r"(b1));
}

// ---------------------------------------------------------------------------
// GEMM: out[m][n] = sum_k A[m*1024+k] * W[n*1024+k] + bias[n]
// Block 128x128x32, 256 threads, 8 warps (2m x 4n), warp tile 64x32.
// Register prefetch + 2-stage smem double buffer.
// transform=1: scatter to [B,H,S,HD]; transform=0: row-major [M,1024].
// ---------------------------------------------------------------------------
__device__ __forceinline__ void gemm_body(
    const float* __restrict__ A, const float* __restrict__ W,
    const float* __restrict__ bias, float* __restrict__ out, int transform,
    int bm, int bn)
{
    __shared__ float As[2][128*36];
    __shared__ float Bs[2][128*36];

    const int tid = threadIdx.x;
    const int wid = tid >> 5, lane = tid & 31;
    const int g = lane >> 2, tig = lane & 3;
    const int wm = (wid & 1) * 64;
    const int wn = (wid >> 1) * 32;

    const int lrow = tid >> 1;
    const int lcb  = (tid & 1) * 16;

    const float* arow = &A[(size_t)(bm + lrow) * D_ + lcb];
    const float* wrow_ = &W[(size_t)(bn + lrow) * D_ + lcb];

    float c[4][4][4] = {};
    float4 pa[4], pb[4];

    // prologue: chunk 0
    #pragma unroll
    for (int j = 0; j < 4; j++) {
        pa[j] = ((const float4*)arow)[j];
        pb[j] = ((const float4*)wrow_)[j];
    }
    #pragma unroll
    for (int j = 0; j < 4; j++) {
        *(float4*)&As[0][lrow*36 + lcb + j*4] = cvt4(pa[j]);
        *(float4*)&Bs[0][lrow*36 + lcb + j*4] = cvt4(pb[j]);
    }
    __syncthreads();

    for (int it = 0; it < 32; it++) {
        const int cur = it & 1;
        if (it < 31) {
            const float4* ap = (const float4*)(arow + (it+1)*32);
            const float4* wp = (const float4*)(wrow_ + (it+1)*32);
            #pragma unroll
            for (int j = 0; j < 4; j++) { pa[j] = ap[j]; pb[j] = wp[j]; }
        }
        const float* Ac = As[cur];
        const float* Bc = Bs[cur];
        #pragma unroll
        for (int ks = 0; ks < 4; ks++) {
            uint32_t a[4][4], b[4][2];
            #pragma unroll
            for (int mt = 0; mt < 4; mt++) {
                int r = wm + mt*16;
                a[mt][0] = __float_as_uint(Ac[(r+g  )*36 + ks*8 + tig    ]);
                a[mt][1] = __float_as_uint(Ac[(r+g+8)*36 + ks*8 + tig    ]);
                a[mt][2] = __float_as_uint(Ac[(r+g  )*36 + ks*8 + tig + 4]);
                a[mt][3] = __float_as_uint(Ac[(r+g+8)*36 + ks*8 + tig + 4]);
            }
            #pragma unroll
            for (int nt = 0; nt < 4; nt++) {
                int n = wn + nt*8;
                b[nt][0] = __float_as_uint(Bc[(n+g)*36 + ks*8 + tig    ]);
                b[nt][1] = __float_as_uint(Bc[(n+g)*36 + ks*8 + tig + 4]);
            }
            #pragma unroll
            for (int mt = 0; mt < 4; mt++)
                #pragma unroll
                for (int nt = 0; nt < 4; nt++)
                    mma8(c[mt][nt], a[mt][0], a[mt][1], a[mt][2], a[mt][3],
                         b[nt][0], b[nt][1]);
        }
        if (it < 31) {
            const int nxt = cur ^ 1;
            #pragma unroll
            for (int j = 0; j < 4; j++) {
                *(float4*)&As[nxt][lrow*36 + lcb + j*4] = cvt4(pa[j]);
                *(float4*)&Bs[nxt][lrow*36 + lcb + j*4] = cvt4(pb[j]);
            }
            __syncthreads();
        }
    }

    #pragma unroll
    for (int mt = 0; mt < 4; mt++) {
        #pragma unroll
        for (int p = 0; p < 2; p++) {
            int row = bm + wm + mt*16 + g + p*8;
            #pragma unroll
            for (int nt = 0; nt < 4; nt++) {
                int col = bn + wn + nt*8 + tig*2;
                float2 v;
                v.x = c[mt][nt][p*2+0] + bias[col];
                v.y = c[mt][nt][p*2+1] + bias[col+1];
                if (transform) {
                    int b_ = row >> 11, s = row & 2047;
                    int h = col >> 6, e = col & 63;
                    *(float2*)&out[(((size_t)(b_*H_ + h)*S_ + s))*HD_ + e] = v;
                } else {
                    *(float2*)&out[(size_t)row * D_ + col] = v;
                }
            }
        }
    }
}

// Fused QKV projections: blockIdx.z selects which projection.
__global__ void __launch_bounds__(256) proj_qkv(
    const float* __restrict__ Q, const float* __restrict__ K, const float* __restrict__ V,
    const float* __restrict__ Wq, const float* __restrict__ Wk, const float* __restrict__ Wv,
    const float* __restrict__ bq, const float* __restrict__ bk, const float* __restrict__ bv,
    float* __restrict__ oq, float* __restrict__ ok, float* __restrict__ ov)
{
    const float *A, *W, *bias; float* out;
    if (blockIdx.z == 0)      { A = Q; W = Wq; bias = bq; out = oq; }
    else if (blockIdx.z == 1) { A = K; W = Wk; bias = bk; out = ok; }
    else                      { A = V; W = Wv; bias = bv; out = ov; }
    gemm_body(A, W, bias, out, 1, blockIdx.y * 128, blockIdx.x * 128);
}

__global__ void __launch_bounds__(256) out_proj(
    const float* __restrict__ A, const float* __restrict__ W,
    const float* __restrict__ bias, float* __restrict__ out)
{
    gemm_body(A, W, bias, out, 0, blockIdx.y * 128, blockIdx.x * 128);
}

// ---------------------------------------------------------------------------
// Flash attention, tensor cores. 128 threads (4 warps), 32 q-rows per warp
// (2 m-tiles of 16), 128 q-rows per CTA, K/V blocks of 64.
// ---------------------------------------------------------------------------
__global__ void __launch_bounds__(128) attn_tc()
{
    extern __shared__ float sm[];
    float* Qs = sm;              // 128 x 68
    float* Ps = Qs + 128*68;     // 128 x 68
    float* Ks = Ps + 128*68;     // 64 x 68
    float* Vs = Ks + 64*68;      // 64 x 68

    const int bh = blockIdx.y;
    const int b  = bh >> 4, h = bh & 15;
    const int q0 = blockIdx.x * 128;
    const float* qp = g_q + (size_t)bh * S_ * HD_;
    const float* kp = g_k + (size_t)bh * S_ * HD_;
    const float* vp = g_v + (size_t)bh * S_ * HD_;

    const int tid = threadIdx.x;
    const int wid = tid >> 5, lane = tid & 31;
    const int g = lane >> 2, tig = lane & 3;
    const int wrow = wid * 32;
    const float scale = 0.125f;

    // Load + scale + cvt Q (128 x 64): one row per thread
    {
        const float4* src = (const float4*)&qp[(size_t)(q0 + tid) * HD_];
        float* dst = &Qs[tid*68];
        #pragma unroll
        for (int j = 0; j < 16; j++)
            *(float4*)&dst[j*4] = cvt4s(src[j], scale);
    }

    float mx[2][2], ls[2][2];
    #pragma unroll
    for (int mt = 0; mt < 2; mt++) { mx[mt][0]=mx[mt][1]=-1e30f; ls[mt][0]=ls[mt][1]=0.f; }
    float acc[2][8][4] = {};

    for (int kb = 0; kb < S_; kb += 64) {
        __syncthreads();
        {
            int row = tid >> 1;
            int cb  = (tid & 1) * 32;
            const float4* ksrc = (const float4*)&kp[(size_t)(kb + row) * HD_ + cb];
            const float4* vsrc = (const float4*)&vp[(size_t)(kb + row) * HD_ + cb];
            #pragma unroll
            for (int j = 0; j < 8; j++) {
                *(float4*)&Ks[row*68 + cb + j*4] = cvt4(ksrc[j]);
                *(float4*)&Vs[row*68 + cb + j*4] = cvt4(vsrc[j]);
            }
        }
        __syncthreads();

        // S = Q K^T : warp tile 32 x 64
        float s[2][8][4] = {};
        #pragma unroll
        for (int ksd = 0; ksd < 8; ksd++) {
            uint32_t a[2][4];
            #pragma unroll
            for (int mt = 0; mt < 2; mt++) {
                int r = wrow + mt*16;
                a[mt][0] = __float_as_uint(Qs[(r+g  )*68 + ksd*8 + tig    ]);
                a[mt][1] = __float_as_uint(Qs[(r+g+8)*68 + ksd*8 + tig    ]);
                a[mt][2] = __float_as_uint(Qs[(r+g  )*68 + ksd*8 + tig + 4]);
                a[mt][3] = __float_as_uint(Qs[(r+g+8)*68 + ksd*8 + tig + 4]);
            }
            #pragma unroll
            for (int nt = 0; nt < 8; nt++) {
                uint32_t b0 = __float_as_uint(Ks[(nt*8+g)*68 + ksd*8 + tig    ]);
                uint32_t b1 = __float_as_uint(Ks[(nt*8+g)*68 + ksd*8 + tig + 4]);
                mma8(s[0][nt], a[0][0], a[0][1], a[0][2], a[0][3], b0, b1);
                mma8(s[1][nt], a[1][0], a[1][1], a[1][2], a[1][3], b0, b1);
            }
        }

        // Online softmax per m-tile
        #pragma unroll
        for (int mt = 0; mt < 2; mt++) {
            float rm0 = -1e30f, rm1 = -1e30f;
            #pragma unroll
            for (int nt = 0; nt < 8; nt++) {
                rm0 = fmaxf(rm0, fmaxf(s[mt][nt][0], s[mt][nt][1]));
                rm1 = fmaxf(rm1, fmaxf(s[mt][nt][2], s[mt][nt][3]));
            }
            rm0 = fmaxf(rm0, __shfl_xor_sync(0xffffffffu, rm0, 1));
            rm0 = fmaxf(rm0, __shfl_xor_sync(0xffffffffu, rm0, 2));
            rm1 = fmaxf(rm1, __shfl_xor_sync(0xffffffffu, rm1, 1));
            rm1 = fmaxf(rm1, __shfl_xor_sync(0xffffffffu, rm1, 2));

            float nm0 = fmaxf(mx[mt][0], rm0), nm1 = fmaxf(mx[mt][1], rm1);
            float al0 = __expf(mx[mt][0] - nm0), al1 = __expf(mx[mt][1] - nm1);
            mx[mt][0] = nm0; mx[mt][1] = nm1;

            float sum0 = 0.f, sum1 = 0.f;
            int r = wrow + mt*16;
            #pragma unroll
            for (int nt = 0; nt < 8; nt++) {
                float p0 = __expf(s[mt][nt][0] - nm0);
                float p1 = __expf(s[mt][nt][1] - nm0);
                float p2 = __expf(s[mt][nt][2] - nm1);
                float p3 = __expf(s[mt][nt][3] - nm1);
                sum0 += p0 + p1; sum1 += p2 + p3;
                int col = nt*8 + tig*2;
                Ps[(r+g  )*68 + col    ] = f2tff(p0);
                Ps[(r+g  )*68 + col + 1] = f2tff(p1);
                Ps[(r+g+8)*68 + col    ] = f2tff(p2);
                Ps[(r+g+8)*68 + col + 1] = f2tff(p3);
            }
            sum0 += __shfl_xor_sync(0xffffffffu, sum0, 1);
            sum0 += __shfl_xor_sync(0xffffffffu, sum0, 2);
            sum1 += __shfl_xor_sync(0xffffffffu, sum1, 1);
            sum1 += __shfl_xor_sync(0xffffffffu, sum1, 2);
            ls[mt][0] = ls[mt][0] * al0 + sum0;
            ls[mt][1] = ls[mt][1] * al1 + sum1;

            #pragma unroll
            for (int nt = 0; nt < 8; nt++) {
                acc[mt][nt][0] *= al0; acc[mt][nt][1] *= al0;
                acc[mt][nt][2] *= al1; acc[mt][nt][3] *= al1;
            }
        }
        __syncwarp();

        // acc += P * V
        #pragma unroll
        for (int ksd = 0; ksd < 8; ksd++) {
            uint32_t a[2][4];
            #pragma unroll
            for (int mt = 0; mt < 2; mt++) {
                int r = wrow + mt*16;
                a[mt][0] = __float_as_uint(Ps[(r+g  )*68 + ksd*8 + tig    ]);
                a[mt][1] = __float_as_uint(Ps[(r+g+8)*68 + ksd*8 + tig    ]);
                a[mt][2] = __float_as_uint(Ps[(r+g  )*68 + ksd*8 + tig + 4]);
                a[mt][3] = __float_as_uint(Ps[(r+g+8)*68 + ksd*8 + tig + 4]);
            }
            #pragma unroll
            for (int nt = 0; nt < 8; nt++) {
                uint32_t b0 = __float_as_uint(Vs[(ksd*8+tig  )*68 + nt*8 + g]);
                uint32_t b1 = __float_as_uint(Vs[(ksd*8+tig+4)*68 + nt*8 + g]);
                mma8(acc[0][nt], a[0][0], a[0][1], a[0][2], a[0][3], b0, b1);
                mma8(acc[1][nt], a[1][0], a[1][1], a[1][2], a[1][3], b0, b1);
            }
        }
    }

    // Epilogue: normalize, store concat layout
    #pragma unroll
    for (int mt = 0; mt < 2; mt++) {
        float inv0 = 1.0f / ls[mt][0], inv1 = 1.0f / ls[mt][1];
        int r0 = q0 + wrow + mt*16 + g;
        int r1 = r0 + 8;
        #pragma unroll
        for (int nt = 0; nt < 8; nt++) {
            int col = h*64 + nt*8 + tig*2;
            float2 v0, v1;
            v0.x = acc[mt][nt][0]*inv0; v0.y = acc[mt][nt][1]*inv0;
            v1.x = acc[mt][nt][2]*inv1; v1.y = acc[mt][nt][3]*inv1;
            *(float2*)&g_att[(size_t)(b*S_ + r0)*D_ + col] = v0;
            *(float2*)&g_att[(size_t)(b*S_ + r1)*D_ + col] = v1;
        }
    }
}

// ---------------------------------------------------------------------------
extern "C" void kernel_launch(void* const* d_in, const int* in_sizes, int n_in,
                              void* d_out, int out_size)
{
    const float* V  = (const float*)d_in[0];
    const float* K  = (const float*)d_in[1];
    const float* Q  = (const float*)d_in[2];
    const float* Wv = (const float*)d_in[3];
    const float* bv = (const float*)d_in[4];
    const float* Wk = (const float*)d_in[5];
    const float* bk = (const float*)d_in[6];
    const float* Wq = (const float*)d_in[7];
    const float* bq = (const float*)d_in[8];
    const float* Wo = (const float*)d_in[9];
    const float* bo = (const float*)d_in[10];
    float* out = (float*)d_out;

    (void)in_sizes; (void)n_in; (void)out_size;

    float* gq; cudaGetSymbolAddress((void**)&gq, g_q);
    float* gk; cudaGetSymbolAddress((void**)&gk, g_k);
    float* gv; cudaGetSymbolAddress((void**)&gv, g_v);
    float* ga; cudaGetSymbolAddress((void**)&ga, g_att);

    dim3 gproj(D_/128, MROWS/128, 3);   // (8, 32, 3)
    proj_qkv<<<gproj, 256>>>(Q, K, V, Wq, Wk, Wv, bq, bk, bv, gq, gk, gv);

    const int smem = (128*68*2 + 64*68*2) * (int)sizeof(float);   // 104448
    cudaFuncSetAttribute(attn_tc, cudaFuncAttributeMaxDynamicSharedMemorySize, smem);
    dim3 ga_grid(S_/128, B_*H_);
    attn_tc<<<ga_grid, 128, smem>>>();

    dim3 gout(D_/128, MROWS/128);
    out_proj<<<gout, 256>>>(ga, Wo, bo, out);
}

// round 6
// speedup vs baseline: 2.0151x; 2.0151x over previous
#include <cuda_runtime.h>
#include <math.h>
#include <stdint.h>

#define H_  16
#define HD_ 64
#define D_  1024
#define B_  2
#define S_  2048
#define MROWS (B_*S_)   // 4096

// q/k/v stored PRE-ROUNDED to tf32 (and q pre-scaled by 0.125) in [B,H,S,HD]
__device__ float g_q[(size_t)B_*H_*S_*HD_];
__device__ float g_k[(size_t)B_*H_*S_*HD_];
__device__ float g_v[(size_t)B_*H_*S_*HD_];
__device__ float g_att[(size_t)MROWS*D_];

// ---------------------------------------------------------------------------
__device__ __forceinline__ uint32_t f2tf(float f) {
    uint32_t r; asm("cvt.rna.tf32.f32 %0, %1;" : "=r"(r) : "f"(f)); return r;
}
__device__ __forceinline__ float f2tff(float f) { return __uint_as_float(f2tf(f)); }

__device__ __forceinline__ void mma8(float* c,
    uint32_t a0, uint32_t a1, uint32_t a2, uint32_t a3,
    uint32_t b0, uint32_t b1)
{
    asm volatile(
        "mma.sync.aligned.m16n8k8.row.col.f32.tf32.tf32.f32 "
        "{%0,%1,%2,%3}, {%4,%5,%6,%7}, {%8,%9}, {%0,%1,%2,%3};"
        : "+f"(c[0]), "+f"(c[1]), "+f"(c[2]), "+f"(c[3])
        : "r"(a0), "r"(a1), "r"(a2), "r"(a3), "r"(b0), "r"(b1));
}

__device__ __forceinline__ uint32_t smem_u32(const void* p) {
    uint32_t a;
    asm("{ .reg .u64 t; cvta.to.shared.u64 t, %1; cvt.u32.u64 %0, t; }"
        : "=r"(a) : "l"(p));
    return a;
}

#define CP16(dst, src) \
    asm volatile("cp.async.cg.shared.global [%0], [%1], 16;" \
        :: "r"(dst), "l"(src) : "memory")
#define CP_COMMIT() asm volatile("cp.async.commit_group;" ::: "memory")
#define CP_WAIT1()  asm volatile("cp.async.wait_group 1;" ::: "memory")

// ---------------------------------------------------------------------------
// GEMM: out[m][n] = sum_k A[m*1024+k] * W[n*1024+k] + bias[n]
// 128x128x32 tiles, 256 thr, 8 warps (2m x 4n), warp 64x32.
// cp.async 2-stage; tf32 cvt at fragment load (numerically = cvt-at-store).
// mode 1: store f2tff((c+bias)*oscale) scattered to [B,H,S,HD]
// mode 0: store (c+bias) raw row-major.
// smem: A stages at 0, 18432; B stages at 36864, 36864+18432. 73728 B total.
// ---------------------------------------------------------------------------
__device__ __forceinline__ void gemm_cp_body(
    const float* __restrict__ A, const float* __restrict__ W,
    const float* __restrict__ bias, float* __restrict__ out,
    int mode, float oscale, int bm, int bn, char* smc)
{
    const int tid = threadIdx.x;
    const int wid = tid >> 5, lane = tid & 31;
    const int g = lane >> 2, tig = lane & 3;
    const int wm = (wid & 1) * 64;
    const int wn = (wid >> 1) * 32;
    const int row = tid >> 1, half = (tid & 1) * 16;

    const float* gA = A + (size_t)(bm + row) * D_ + half;
    const float* gB = W + (size_t)(bn + row) * D_ + half;
    const uint32_t uA = smem_u32(smc) + (row*36 + half) * 4;
    const uint32_t uB = uA + 36864;

    float c[4][4][4] = {};

    // prologue: chunks 0,1
    #pragma unroll
    for (int st = 0; st < 2; st++) {
        #pragma unroll
        for (int j = 0; j < 4; j++) {
            CP16(uA + st*18432 + j*16, gA + st*32 + j*4);
            CP16(uB + st*18432 + j*16, gB + st*32 + j*4);
        }
        CP_COMMIT();
    }

    for (int it = 0; it < 32; it++) {
        CP_WAIT1();
        __syncthreads();
        const float* Ac = (const float*)(smc + (it & 1)*18432);
        const float* Bc = (const float*)(smc + 36864 + (it & 1)*18432);
        #pragma unroll
        for (int ks = 0; ks < 4; ks++) {
            uint32_t a[4][4], b[4][2];
            #pragma unroll
            for (int mt = 0; mt < 4; mt++) {
                int r = wm + mt*16;
                a[mt][0] = f2tf(Ac[(r+g  )*36 + ks*8 + tig    ]);
                a[mt][1] = f2tf(Ac[(r+g+8)*36 + ks*8 + tig    ]);
                a[mt][2] = f2tf(Ac[(r+g  )*36 + ks*8 + tig + 4]);
                a[mt][3] = f2tf(Ac[(r+g+8)*36 + ks*8 + tig + 4]);
            }
            #pragma unroll
            for (int nt = 0; nt < 4; nt++) {
                int n = wn + nt*8;
                b[nt][0] = f2tf(Bc[(n+g)*36 + ks*8 + tig    ]);
                b[nt][1] = f2tf(Bc[(n+g)*36 + ks*8 + tig + 4]);
            }
            #pragma unroll
            for (int mt = 0; mt < 4; mt++)
                #pragma unroll
                for (int nt = 0; nt < 4; nt++)
                    mma8(c[mt][nt], a[mt][0], a[mt][1], a[mt][2], a[mt][3],
                         b[nt][0], b[nt][1]);
        }
        __syncthreads();
        if (it + 2 < 32) {
            int st = it & 1;
            #pragma unroll
            for (int j = 0; j < 4; j++) {
                CP16(uA + st*18432 + j*16, gA + (it+2)*32 + j*4);
                CP16(uB + st*18432 + j*16, gB + (it+2)*32 + j*4);
            }
        }
        CP_COMMIT();
    }

    #pragma unroll
    for (int mt = 0; mt < 4; mt++) {
        #pragma unroll
        for (int p = 0; p < 2; p++) {
            int m = bm + wm + mt*16 + g + p*8;
            #pragma unroll
            for (int nt = 0; nt < 4; nt++) {
                int col = bn + wn + nt*8 + tig*2;
                float2 v;
                v.x = c[mt][nt][p*2+0] + bias[col];
                v.y = c[mt][nt][p*2+1] + bias[col+1];
                if (mode) {
                    v.x = f2tff(v.x * oscale);
                    v.y = f2tff(v.y * oscale);
                    int b_ = m >> 11, s = m & 2047;
                    int hh = col >> 6, e = col & 63;
                    *(float2*)&out[(((size_t)(b_*H_ + hh)*S_ + s))*HD_ + e] = v;
                } else {
                    *(float2*)&out[(size_t)m * D_ + col] = v;
                }
            }
        }
    }
}

__global__ void __launch_bounds__(256, 2) proj_qkv(
    const float* __restrict__ Q, const float* __restrict__ K, const float* __restrict__ V,
    const float* __restrict__ Wq, const float* __restrict__ Wk, const float* __restrict__ Wv,
    const float* __restrict__ bq, const float* __restrict__ bk, const float* __restrict__ bv,
    float* __restrict__ oq, float* __restrict__ ok, float* __restrict__ ov)
{
    extern __shared__ char smc[];
    const float *A, *W, *bias; float* out; float sc;
    if (blockIdx.z == 0)      { A = Q; W = Wq; bias = bq; out = oq; sc = 0.125f; }
    else if (blockIdx.z == 1) { A = K; W = Wk; bias = bk; out = ok; sc = 1.0f; }
    else                      { A = V; W = Wv; bias = bv; out = ov; sc = 1.0f; }
    gemm_cp_body(A, W, bias, out, 1, sc, blockIdx.y*128, blockIdx.x*128, smc);
}

__global__ void __launch_bounds__(256, 2) out_proj(
    const float* __restrict__ A, const float* __restrict__ W,
    const float* __restrict__ bias, float* __restrict__ out)
{
    extern __shared__ char smc[];
    gemm_cp_body(A, W, bias, out, 0, 1.0f, blockIdx.y*128, blockIdx.x*128, smc);
}

// ---------------------------------------------------------------------------
// Flash attention: 256 thr / 8 warps, 16 q-rows per warp (128/CTA),
// K/V 64-row blocks, cp.async 2-stage K/V, P kept in registers via shuffles.
// Q pre-scaled+tf32-rounded by proj; K/V tf32-rounded => no cvt on frag loads.
// smem: Qs 128x68 @0 (34816B), K stages @34816+st*17408, V stages @69632+st*18432
// total 106496 B -> 2 CTAs/SM.
// ---------------------------------------------------------------------------
#define ATTN_SMEM 106496
#define NITER (S_/64)

__global__ void __launch_bounds__(256, 2) attn_cp()
{
    extern __shared__ char smc[];
    const int bh = blockIdx.y;
    const int b  = bh >> 4, h = bh & 15;
    const int q0 = blockIdx.x * 128;
    const float* qp = g_q + (size_t)bh * S_ * HD_;
    const float* kp = g_k + (size_t)bh * S_ * HD_;
    const float* vp = g_v + (size_t)bh * S_ * HD_;

    const int tid = threadIdx.x;
    const int wid = tid >> 5, lane = tid & 31;
    const int g = lane >> 2, tig = lane & 3;
    const int wrow = wid * 16;
    const uint32_t sbase = smem_u32(smc);

    // Q: one-time cp.async (part of group 0)
    {
        int row = tid >> 1, hq = (tid & 1) * 32;
        uint32_t dst = sbase + (row*68 + hq) * 4;
        const float* src = qp + (size_t)(q0 + row) * HD_ + hq;
        #pragma unroll
        for (int j = 0; j < 8; j++) CP16(dst + j*16, src + j*4);
    }
    // K/V stage loader
    const int kvrow = tid >> 2, kvq = (tid & 3) * 16;
    {
        // stage 0: kb=0 (group 0 with Q), stage 1: kb=64 (group 1)
        #pragma unroll
        for (int st = 0; st < 2; st++) {
            uint32_t dk = sbase + 34816 + st*17408 + (kvrow*68 + kvq)*4;
            uint32_t dv = sbase + 69632 + st*18432 + (kvrow*72 + kvq)*4;
            const float* sk = kp + (size_t)(st*64 + kvrow) * HD_ + kvq;
            const float* sv = vp + (size_t)(st*64 + kvrow) * HD_ + kvq;
            #pragma unroll
            for (int j = 0; j < 4; j++) { CP16(dk + j*16, sk + j*4); }
            #pragma unroll
            for (int j = 0; j < 4; j++) { CP16(dv + j*16, sv + j*4); }
            CP_COMMIT();
        }
    }

    const float* Qs = (const float*)smc;
    float m0 = -1e30f, m1 = -1e30f, l0 = 0.f, l1 = 0.f;
    float acc[8][4] = {};
    const int src0 = (lane & ~3) | (tig >> 1);
    const int src2 = src0 + 2;
    const bool podd = (tig & 1);

    for (int it = 0; it < NITER; it++) {
        CP_WAIT1();
        __syncthreads();
        const float* Kc = (const float*)(smc + 34816 + (it & 1)*17408);
        const float* Vc = (const float*)(smc + 69632 + (it & 1)*18432);

        // S = Q K^T : warp tile 16 x 64 (values already tf32)
        float s[8][4] = {};
        #pragma unroll
        for (int ksd = 0; ksd < 8; ksd++) {
            uint32_t a0 = __float_as_uint(Qs[(wrow+g  )*68 + ksd*8 + tig    ]);
            uint32_t a1 = __float_as_uint(Qs[(wrow+g+8)*68 + ksd*8 + tig    ]);
            uint32_t a2 = __float_as_uint(Qs[(wrow+g  )*68 + ksd*8 + tig + 4]);
            uint32_t a3 = __float_as_uint(Qs[(wrow+g+8)*68 + ksd*8 + tig + 4]);
            #pragma unroll
            for (int nt = 0; nt < 8; nt++) {
                uint32_t b0 = __float_as_uint(Kc[(nt*8+g)*68 + ksd*8 + tig    ]);
                uint32_t b1 = __float_as_uint(Kc[(nt*8+g)*68 + ksd*8 + tig + 4]);
                mma8(s[nt], a0, a1, a2, a3, b0, b1);
            }
        }

        // online softmax (rows wrow+g, wrow+g+8); p overwrites s
        float rm0 = -1e30f, rm1 = -1e30f;
        #pragma unroll
        for (int nt = 0; nt < 8; nt++) {
            rm0 = fmaxf(rm0, fmaxf(s[nt][0], s[nt][1]));
            rm1 = fmaxf(rm1, fmaxf(s[nt][2], s[nt][3]));
        }
        rm0 = fmaxf(rm0, __shfl_xor_sync(0xffffffffu, rm0, 1));
        rm0 = fmaxf(rm0, __shfl_xor_sync(0xffffffffu, rm0, 2));
        rm1 = fmaxf(rm1, __shfl_xor_sync(0xffffffffu, rm1, 1));
        rm1 = fmaxf(rm1, __shfl_xor_sync(0xffffffffu, rm1, 2));

        float nm0 = fmaxf(m0, rm0), nm1 = fmaxf(m1, rm1);
        float al0 = __expf(m0 - nm0), al1 = __expf(m1 - nm1);
        m0 = nm0; m1 = nm1;

        float sum0 = 0.f, sum1 = 0.f;
        #pragma unroll
        for (int nt = 0; nt < 8; nt++) {
            float p0 = __expf(s[nt][0] - nm0);
            float p1 = __expf(s[nt][1] - nm0);
            float p2 = __expf(s[nt][2] - nm1);
            float p3 = __expf(s[nt][3] - nm1);
            sum0 += p0 + p1; sum1 += p2 + p3;
            s[nt][0] = p0; s[nt][1] = p1; s[nt][2] = p2; s[nt][3] = p3;
        }
        sum0 += __shfl_xor_sync(0xffffffffu, sum0, 1);
        sum0 += __shfl_xor_sync(0xffffffffu, sum0, 2);
        sum1 += __shfl_xor_sync(0xffffffffu, sum1, 1);
        sum1 += __shfl_xor_sync(0xffffffffu, sum1, 2);
        l0 = l0 * al0 + sum0;
        l1 = l1 * al1 + sum1;

        #pragma unroll
        for (int nt = 0; nt < 8; nt++) {
            acc[nt][0] *= al0; acc[nt][1] *= al0;
            acc[nt][2] *= al1; acc[nt][3] *= al1;
        }

        // acc += P * V; P A-frags built by shuffle from C-frags s[ksd][*]
        #pragma unroll
        for (int ksd = 0; ksd < 8; ksd++) {
            float v00 = __shfl_sync(0xffffffffu, s[ksd][0], src0);
            float v01 = __shfl_sync(0xffffffffu, s[ksd][1], src0);
            float v10 = __shfl_sync(0xffffffffu, s[ksd][2], src0);
            float v11 = __shfl_sync(0xffffffffu, s[ksd][3], src0);
            float w00 = __shfl_sync(0xffffffffu, s[ksd][0], src2);
            float w01 = __shfl_sync(0xffffffffu, s[ksd][1], src2);
            float w10 = __shfl_sync(0xffffffffu, s[ksd][2], src2);
            float w11 = __shfl_sync(0xffffffffu, s[ksd][3], src2);
            uint32_t a0 = f2tf(podd ? v01 : v00);
            uint32_t a1 = f2tf(podd ? v11 : v10);
            uint32_t a2 = f2tf(podd ? w01 : w00);
            uint32_t a3 = f2tf(podd ? w11 : w10);
            #pragma unroll
            for (int nt = 0; nt < 8; nt++) {
                uint32_t b0 = __float_as_uint(Vc[(ksd*8+tig  )*72 + nt*8 + g]);
                uint32_t b1 = __float_as_uint(Vc[(ksd*8+tig+4)*72 + nt*8 + g]);
                mma8(acc[nt], a0, a1, a2, a3, b0, b1);
            }
        }

        __syncthreads();
        if (it + 2 < NITER) {
            int st = it & 1;
            uint32_t dk = sbase + 34816 + st*17408 + (kvrow*68 + kvq)*4;
            uint32_t dv = sbase + 69632 + st*18432 + (kvrow*72 + kvq)*4;
            const float* sk = kp + (size_t)((it+2)*64 + kvrow) * HD_ + kvq;
            const float* sv = vp + (size_t)((it+2)*64 + kvrow) * HD_ + kvq;
            #pragma unroll
            for (int j = 0; j < 4; j++) { CP16(dk + j*16, sk + j*4); }
            #pragma unroll
            for (int j = 0; j < 4; j++) { CP16(dv + j*16, sv + j*4); }
        }
        CP_COMMIT();
    }

    // epilogue: normalize, store concat layout (raw fp32; out_proj cvts)
    float inv0 = 1.0f / l0, inv1 = 1.0f / l1;
    int r0 = q0 + wrow + g;
    int r1 = r0 + 8;
    #pragma unroll
    for (int nt = 0; nt < 8; nt++) {
        int col = h*64 + nt*8 + tig*2;
        float2 v0, v1;
        v0.x = acc[nt][0]*inv0; v0.y = acc[nt][1]*inv0;
        v1.x = acc[nt][2]*inv1; v1.y = acc[nt][3]*inv1;
        *(float2*)&g_att[(size_t)(b*S_ + r0)*D_ + col] = v0;
        *(float2*)&g_att[(size_t)(b*S_ + r1)*D_ + col] = v1;
    }
}

// ---------------------------------------------------------------------------
extern "C" void kernel_launch(void* const* d_in, const int* in_sizes, int n_in,
                              void* d_out, int out_size)
{
    const float* V  = (const float*)d_in[0];
    const float* K  = (const float*)d_in[1];
    const float* Q  = (const float*)d_in[2];
    const float* Wv = (const float*)d_in[3];
    const float* bv = (const float*)d_in[4];
    const float* Wk = (const float*)d_in[5];
    const float* bk = (const float*)d_in[6];
    const float* Wq = (const float*)d_in[7];
    const float* bq = (const float*)d_in[8];
    const float* Wo = (const float*)d_in[9];
    const float* bo = (const float*)d_in[10];
    float* out = (float*)d_out;

    (void)in_sizes; (void)n_in; (void)out_size;

    float* gq; cudaGetSymbolAddress((void**)&gq, g_q);
    float* gk; cudaGetSymbolAddress((void**)&gk, g_k);
    float* gv; cudaGetSymbolAddress((void**)&gv, g_v);
    float* ga; cudaGetSymbolAddress((void**)&ga, g_att);

    const int gemm_smem = 73728;
    cudaFuncSetAttribute(proj_qkv, cudaFuncAttributeMaxDynamicSharedMemorySize, gemm_smem);
    cudaFuncSetAttribute(out_proj, cudaFuncAttributeMaxDynamicSharedMemorySize, gemm_smem);
    cudaFuncSetAttribute(attn_cp,  cudaFuncAttributeMaxDynamicSharedMemorySize, ATTN_SMEM);

    dim3 gproj(D_/128, MROWS/128, 3);   // (8, 32, 3)
    proj_qkv<<<gproj, 256, gemm_smem>>>(Q, K, V, Wq, Wk, Wv, bq, bk, bv, gq, gk, gv);

    dim3 ga_grid(S_/128, B_*H_);        // (16, 32)
    attn_cp<<<ga_grid, 256, ATTN_SMEM>>>();

    dim3 gout(D_/128, MROWS/128);
    out_proj<<<gout, 256, gemm_smem>>>(ga, Wo, bo, out);
}

// round 7
// speedup vs baseline: 2.0241x; 1.0045x over previous
#include <cuda_runtime.h>
#include <math.h>
#include <stdint.h>

#define H_  16
#define HD_ 64
#define D_  1024
#define B_  2
#define S_  2048
#define MROWS (B_*S_)   // 4096

// q/k/v stored PRE-ROUNDED to tf32 (q pre-scaled by 0.125) in [B,H,S,HD]
__device__ float g_q[(size_t)B_*H_*S_*HD_];
__device__ float g_k[(size_t)B_*H_*S_*HD_];
__device__ float g_v[(size_t)B_*H_*S_*HD_];
__device__ float g_att[(size_t)MROWS*D_];

// ---------------------------------------------------------------------------
__device__ __forceinline__ uint32_t f2tf(float f) {
    uint32_t r; asm("cvt.rna.tf32.f32 %0, %1;" : "=r"(r) : "f"(f)); return r;
}
__device__ __forceinline__ float f2tff(float f) { return __uint_as_float(f2tf(f)); }

__device__ __forceinline__ void mma8(float* c,
    uint32_t a0, uint32_t a1, uint32_t a2, uint32_t a3,
    uint32_t b0, uint32_t b1)
{
    asm volatile(
        "mma.sync.aligned.m16n8k8.row.col.f32.tf32.tf32.f32 "
        "{%0,%1,%2,%3}, {%4,%5,%6,%7}, {%8,%9}, {%0,%1,%2,%3};"
        : "+f"(c[0]), "+f"(c[1]), "+f"(c[2]), "+f"(c[3])
        : "r"(a0), "r"(a1), "r"(a2), "r"(a3), "r"(b0), "r"(b1));
}

__device__ __forceinline__ uint32_t smem_u32(const void* p) {
    uint32_t a;
    asm("{ .reg .u64 t; cvta.to.shared.u64 t, %1; cvt.u32.u64 %0, t; }"
        : "=r"(a) : "l"(p));
    return a;
}

#define CP16(dst, src) \
    asm volatile("cp.async.cg.shared.global [%0], [%1], 16;" \
        :: "r"(dst), "l"(src) : "memory")
#define CP_COMMIT() asm volatile("cp.async.commit_group;" ::: "memory")
#define CP_WAIT1()  asm volatile("cp.async.wait_group 1;" ::: "memory")

// ---------------------------------------------------------------------------
// GEMM: out[m][n] = sum_k A[m*1024+k] * W[n*1024+k] + bias[n]
// CTA tile 256x128, K=32 chunks; 8 warps (4m x 2n), warp tile 64x64.
// 3-stage cp.async ring, ONE barrier per iteration.
// smem stage: A 256x36 fl (36864 B) + B 128x36 fl (18432 B) = 55296 B; x3.
// mode 1: store f2tff((c+bias)*oscale) scattered to [B,H,S,HD]; mode 0 raw.
// ---------------------------------------------------------------------------
#define GS_A    36864
#define GS_STG  55296
#define GEMM_SMEM (3*GS_STG)   // 165888

__device__ __forceinline__ void gemm_cp_body(
    const float* __restrict__ A, const float* __restrict__ W,
    const float* __restrict__ bias, float* __restrict__ out,
    int mode, float oscale, int bm, int bn, char* smc)
{
    const int tid = threadIdx.x;
    const int wid = tid >> 5, lane = tid & 31;
    const int g = lane >> 2, tig = lane & 3;
    const int wm = (wid & 3) * 64;
    const int wn = (wid >> 2) * 64;
    const uint32_t sbase = smem_u32(smc);

    // loaders: A row = tid (8 x 16B); B row = tid>>1, half (tid&1)*16 (4 x 16B)
    const float* gA = A + (size_t)(bm + tid) * D_;
    const float* gB = W + (size_t)(bn + (tid >> 1)) * D_ + (tid & 1) * 16;
    const uint32_t uA = sbase + (uint32_t)(tid * 36) * 4;
    const uint32_t uB = sbase + GS_A + (uint32_t)((tid >> 1) * 36 + (tid & 1) * 16) * 4;

    float c[4][8][4] = {};

    // prologue: chunks 0,1 -> stages 0,1
    #pragma unroll
    for (int st = 0; st < 2; st++) {
        #pragma unroll
        for (int j = 0; j < 8; j++) CP16(uA + st*GS_STG + j*16, gA + st*32 + j*4);
        #pragma unroll
        for (int j = 0; j < 4; j++) CP16(uB + st*GS_STG + j*16, gB + st*32 + j*4);
        CP_COMMIT();
    }

    for (int it = 0; it < 32; it++) {
        CP_WAIT1();
        __syncthreads();
        const int cs = it % 3;
        const float* Ac = (const float*)(smc + cs*GS_STG);
        const float* Bc = (const float*)(smc + cs*GS_STG + GS_A);
        #pragma unroll
        for (int ks = 0; ks < 4; ks++) {
            uint32_t a[4][4], b[8][2];
            #pragma unroll
            for (int mt = 0; mt < 4; mt++) {
                int r = wm + mt*16;
                a[mt][0] = f2tf(Ac[(r+g  )*36 + ks*8 + tig    ]);
                a[mt][1] = f2tf(Ac[(r+g+8)*36 + ks*8 + tig    ]);
                a[mt][2] = f2tf(Ac[(r+g  )*36 + ks*8 + tig + 4]);
                a[mt][3] = f2tf(Ac[(r+g+8)*36 + ks*8 + tig + 4]);
            }
            #pragma unroll
            for (int nt = 0; nt < 8; nt++) {
                int n = wn + nt*8;
                b[nt][0] = f2tf(Bc[(n+g)*36 + ks*8 + tig    ]);
                b[nt][1] = f2tf(Bc[(n+g)*36 + ks*8 + tig + 4]);
            }
            #pragma unroll
            for (int mt = 0; mt < 4; mt++)
                #pragma unroll
                for (int nt = 0; nt < 8; nt++)
                    mma8(c[mt][nt], a[mt][0], a[mt][1], a[mt][2], a[mt][3],
                         b[nt][0], b[nt][1]);
        }
        // prefetch chunk it+2 into stage (it+2)%3 (distinct from read stage)
        if (it + 2 < 32) {
            const int ns = (it + 2) % 3;
            #pragma unroll
            for (int j = 0; j < 8; j++) CP16(uA + ns*GS_STG + j*16, gA + (it+2)*32 + j*4);
            #pragma unroll
            for (int j = 0; j < 4; j++) CP16(uB + ns*GS_STG + j*16, gB + (it+2)*32 + j*4);
        }
        CP_COMMIT();
    }

    #pragma unroll
    for (int mt = 0; mt < 4; mt++) {
        #pragma unroll
        for (int p = 0; p < 2; p++) {
            int m = bm + wm + mt*16 + g + p*8;
            #pragma unroll
            for (int nt = 0; nt < 8; nt++) {
                int col = bn + wn + nt*8 + tig*2;
                float2 v;
                v.x = c[mt][nt][p*2+0] + bias[col];
                v.y = c[mt][nt][p*2+1] + bias[col+1];
                if (mode) {
                    v.x = f2tff(v.x * oscale);
                    v.y = f2tff(v.y * oscale);
                    int b_ = m >> 11, s = m & 2047;
                    int hh = col >> 6, e = col & 63;
                    *(float2*)&out[(((size_t)(b_*H_ + hh)*S_ + s))*HD_ + e] = v;
                } else {
                    *(float2*)&out[(size_t)m * D_ + col] = v;
                }
            }
        }
    }
}

__global__ void __launch_bounds__(256) proj_qkv(
    const float* __restrict__ Q, const float* __restrict__ K, const float* __restrict__ V,
    const float* __restrict__ Wq, const float* __restrict__ Wk, const float* __restrict__ Wv,
    const float* __restrict__ bq, const float* __restrict__ bk, const float* __restrict__ bv,
    float* __restrict__ oq, float* __restrict__ ok, float* __restrict__ ov)
{
    extern __shared__ char smc[];
    const float *A, *W, *bias; float* out; float sc;
    if (blockIdx.z == 0)      { A = Q; W = Wq; bias = bq; out = oq; sc = 0.125f; }
    else if (blockIdx.z == 1) { A = K; W = Wk; bias = bk; out = ok; sc = 1.0f; }
    else                      { A = V; W = Wv; bias = bv; out = ov; sc = 1.0f; }
    gemm_cp_body(A, W, bias, out, 1, sc, blockIdx.y*256, blockIdx.x*128, smc);
}

__global__ void __launch_bounds__(256) out_proj(
    const float* __restrict__ A, const float* __restrict__ W,
    const float* __restrict__ bias, float* __restrict__ out)
{
    extern __shared__ char smc[];
    gemm_cp_body(A, W, bias, out, 0, 1.0f, blockIdx.y*256, blockIdx.x*128, smc);
}

// ---------------------------------------------------------------------------
// Flash attention: 256 thr / 8 warps, 32 q-rows per warp (256 q-rows/CTA),
// K/V 64-row blocks, 3-stage cp.async ring (ONE barrier per iter),
// P kept in registers via shuffles. Q/K/V already tf32 (Q pre-scaled).
// smem: Qs 256x68 (69632 B) + 3 stages of (K 64x68 + V 64x72) (35840 B each).
// ---------------------------------------------------------------------------
#define KV_STG   35840         // 17408 K + 18432 V
#define ATTN_SMEM (69632 + 3*KV_STG)   // 177152
#define NITER (S_/64)

__global__ void __launch_bounds__(256) attn_cp()
{
    extern __shared__ char smc[];
    const int bh = blockIdx.y;
    const int b  = bh >> 4, h = bh & 15;
    const int q0 = blockIdx.x * 256;
    const float* qp = g_q + (size_t)bh * S_ * HD_;
    const float* kp = g_k + (size_t)bh * S_ * HD_;
    const float* vp = g_v + (size_t)bh * S_ * HD_;

    const int tid = threadIdx.x;
    const int wid = tid >> 5, lane = tid & 31;
    const int g = lane >> 2, tig = lane & 3;
    const int wrow = wid * 32;
    const uint32_t sbase = smem_u32(smc);

    // Q: one-time cp.async, one row (64 floats) per thread
    {
        uint32_t dst = sbase + (uint32_t)(tid * 68) * 4;
        const float* src = qp + (size_t)(q0 + tid) * HD_;
        #pragma unroll
        for (int j = 0; j < 16; j++) CP16(dst + j*16, src + j*4);
    }
    // K/V loaders
    const int kvrow = tid >> 2, kvq = (tid & 3) * 16;
    const uint32_t ukb = sbase + 69632 + (uint32_t)(kvrow*68 + kvq)*4;
    const uint32_t uvb = sbase + 69632 + 17408 + (uint32_t)(kvrow*72 + kvq)*4;
    #pragma unroll
    for (int st = 0; st < 2; st++) {
        const float* sk = kp + (size_t)(st*64 + kvrow) * HD_ + kvq;
        const float* sv = vp + (size_t)(st*64 + kvrow) * HD_ + kvq;
        #pragma unroll
        for (int j = 0; j < 4; j++) CP16(ukb + st*KV_STG + j*16, sk + j*4);
        #pragma unroll
        for (int j = 0; j < 4; j++) CP16(uvb + st*KV_STG + j*16, sv + j*4);
        CP_COMMIT();
    }

    const float* Qs = (const float*)smc;
    float mx[2][2], lsum[2][2];
    #pragma unroll
    for (int mt = 0; mt < 2; mt++) {
        mx[mt][0] = mx[mt][1] = -1e30f;
        lsum[mt][0] = lsum[mt][1] = 0.f;
    }
    float acc[2][8][4] = {};
    const int src0 = (lane & ~3) | (tig >> 1);
    const int src2 = src0 + 2;
    const bool podd = (tig & 1);

    for (int it = 0; it < NITER; it++) {
        CP_WAIT1();
        __syncthreads();
        const int cs = it % 3;
        const float* Kc = (const float*)(smc + 69632 + cs*KV_STG);
        const float* Vc = (const float*)(smc + 69632 + cs*KV_STG + 17408);

        // S = Q K^T : warp tile 32 x 64
        float s[2][8][4] = {};
        #pragma unroll
        for (int ksd = 0; ksd < 8; ksd++) {
            uint32_t a[2][4];
            #pragma unroll
            for (int mt = 0; mt < 2; mt++) {
                int r = wrow + mt*16;
                a[mt][0] = __float_as_uint(Qs[(r+g  )*68 + ksd*8 + tig    ]);
                a[mt][1] = __float_as_uint(Qs[(r+g+8)*68 + ksd*8 + tig    ]);
                a[mt][2] = __float_as_uint(Qs[(r+g  )*68 + ksd*8 + tig + 4]);
                a[mt][3] = __float_as_uint(Qs[(r+g+8)*68 + ksd*8 + tig + 4]);
            }
            #pragma unroll
            for (int nt = 0; nt < 8; nt++) {
                uint32_t b0 = __float_as_uint(Kc[(nt*8+g)*68 + ksd*8 + tig    ]);
                uint32_t b1 = __float_as_uint(Kc[(nt*8+g)*68 + ksd*8 + tig + 4]);
                mma8(s[0][nt], a[0][0], a[0][1], a[0][2], a[0][3], b0, b1);
                mma8(s[1][nt], a[1][0], a[1][1], a[1][2], a[1][3], b0, b1);
            }
        }

        // online softmax per m-tile; p overwrites s
        #pragma unroll
        for (int mt = 0; mt < 2; mt++) {
            float rm0 = -1e30f, rm1 = -1e30f;
            #pragma unroll
            for (int nt = 0; nt < 8; nt++) {
                rm0 = fmaxf(rm0, fmaxf(s[mt][nt][0], s[mt][nt][1]));
                rm1 = fmaxf(rm1, fmaxf(s[mt][nt][2], s[mt][nt][3]));
            }
            rm0 = fmaxf(rm0, __shfl_xor_sync(0xffffffffu, rm0, 1));
            rm0 = fmaxf(rm0, __shfl_xor_sync(0xffffffffu, rm0, 2));
            rm1 = fmaxf(rm1, __shfl_xor_sync(0xffffffffu, rm1, 1));
            rm1 = fmaxf(rm1, __shfl_xor_sync(0xffffffffu, rm1, 2));

            float nm0 = fmaxf(mx[mt][0], rm0), nm1 = fmaxf(mx[mt][1], rm1);
            float al0 = __expf(mx[mt][0] - nm0), al1 = __expf(mx[mt][1] - nm1);
            mx[mt][0] = nm0; mx[mt][1] = nm1;

            float sum0 = 0.f, sum1 = 0.f;
            #pragma unroll
            for (int nt = 0; nt < 8; nt++) {
                float p0 = __expf(s[mt][nt][0] - nm0);
                float p1 = __expf(s[mt][nt][1] - nm0);
                float p2 = __expf(s[mt][nt][2] - nm1);
                float p3 = __expf(s[mt][nt][3] - nm1);
                sum0 += p0 + p1; sum1 += p2 + p3;
                s[mt][nt][0] = p0; s[mt][nt][1] = p1;
                s[mt][nt][2] = p2; s[mt][nt][3] = p3;
            }
            sum0 += __shfl_xor_sync(0xffffffffu, sum0, 1);
            sum0 += __shfl_xor_sync(0xffffffffu, sum0, 2);
            sum1 += __shfl_xor_sync(0xffffffffu, sum1, 1);
            sum1 += __shfl_xor_sync(0xffffffffu, sum1, 2);
            lsum[mt][0] = lsum[mt][0] * al0 + sum0;
            lsum[mt][1] = lsum[mt][1] * al1 + sum1;

            #pragma unroll
            for (int nt = 0; nt < 8; nt++) {
                acc[mt][nt][0] *= al0; acc[mt][nt][1] *= al0;
                acc[mt][nt][2] *= al1; acc[mt][nt][3] *= al1;
            }
        }

        // acc += P * V; P A-frags via shuffle from C-frags s[mt][ksd][*]
        #pragma unroll
        for (int ksd = 0; ksd < 8; ksd++) {
            uint32_t pa[2][4];
            #pragma unroll
            for (int mt = 0; mt < 2; mt++) {
                float v00 = __shfl_sync(0xffffffffu, s[mt][ksd][0], src0);
                float v01 = __shfl_sync(0xffffffffu, s[mt][ksd][1], src0);
                float v10 = __shfl_sync(0xffffffffu, s[mt][ksd][2], src0);
                float v11 = __shfl_sync(0xffffffffu, s[mt][ksd][3], src0);
                float w00 = __shfl_sync(0xffffffffu, s[mt][ksd][0], src2);
                float w01 = __shfl_sync(0xffffffffu, s[mt][ksd][1], src2);
                float w10 = __shfl_sync(0xffffffffu, s[mt][ksd][2], src2);
                float w11 = __shfl_sync(0xffffffffu, s[mt][ksd][3], src2);
                pa[mt][0] = f2tf(podd ? v01 : v00);
                pa[mt][1] = f2tf(podd ? v11 : v10);
                pa[mt][2] = f2tf(podd ? w01 : w00);
                pa[mt][3] = f2tf(podd ? w11 : w10);
            }
            #pragma unroll
            for (int nt = 0; nt < 8; nt++) {
                uint32_t b0 = __float_as_uint(Vc[(ksd*8+tig  )*72 + nt*8 + g]);
                uint32_t b1 = __float_as_uint(Vc[(ksd*8+tig+4)*72 + nt*8 + g]);
                mma8(acc[0][nt], pa[0][0], pa[0][1], pa[0][2], pa[0][3], b0, b1);
                mma8(acc[1][nt], pa[1][0], pa[1][1], pa[1][2], pa[1][3], b0, b1);
            }
        }

        // prefetch KV chunk it+2 into stage (it+2)%3 (never the read stage)
        if (it + 2 < NITER) {
            const int ns = (it + 2) % 3;
            const float* sk = kp + (size_t)((it+2)*64 + kvrow) * HD_ + kvq;
            const float* sv = vp + (size_t)((it+2)*64 + kvrow) * HD_ + kvq;
            #pragma unroll
            for (int j = 0; j < 4; j++) CP16(ukb + ns*KV_STG + j*16, sk + j*4);
            #pragma unroll
            for (int j = 0; j < 4; j++) CP16(uvb + ns*KV_STG + j*16, sv + j*4);
        }
        CP_COMMIT();
    }

    // epilogue: normalize, store concat layout
    #pragma unroll
    for (int mt = 0; mt < 2; mt++) {
        float inv0 = 1.0f / lsum[mt][0], inv1 = 1.0f / lsum[mt][1];
        int r0 = q0 + wrow + mt*16 + g;
        int r1 = r0 + 8;
        #pragma unroll
        for (int nt = 0; nt < 8; nt++) {
            int col = h*64 + nt*8 + tig*2;
            float2 v0, v1;
            v0.x = acc[mt][nt][0]*inv0; v0.y = acc[mt][nt][1]*inv0;
            v1.x = acc[mt][nt][2]*inv1; v1.y = acc[mt][nt][3]*inv1;
            *(float2*)&g_att[(size_t)(b*S_ + r0)*D_ + col] = v0;
            *(float2*)&g_att[(size_t)(b*S_ + r1)*D_ + col] = v1;
        }
    }
}

// ---------------------------------------------------------------------------
extern "C" void kernel_launch(void* const* d_in, const int* in_sizes, int n_in,
                              void* d_out, int out_size)
{
    const float* V  = (const float*)d_in[0];
    const float* K  = (const float*)d_in[1];
    const float* Q  = (const float*)d_in[2];
    const float* Wv = (const float*)d_in[3];
    const float* bv = (const float*)d_in[4];
    const float* Wk = (const float*)d_in[5];
    const float* bk = (const float*)d_in[6];
    const float* Wq = (const float*)d_in[7];
    const float* bq = (const float*)d_in[8];
    const float* Wo = (const float*)d_in[9];
    const float* bo = (const float*)d_in[10];
    float* out = (float*)d_out;

    (void)in_sizes; (void)n_in; (void)out_size;

    float* gq; cudaGetSymbolAddress((void**)&gq, g_q);
    float* gk; cudaGetSymbolAddress((void**)&gk, g_k);
    float* gv; cudaGetSymbolAddress((void**)&gv, g_v);
    float* ga; cudaGetSymbolAddress((void**)&ga, g_att);

    cudaFuncSetAttribute(proj_qkv, cudaFuncAttributeMaxDynamicSharedMemorySize, GEMM_SMEM);
    cudaFuncSetAttribute(out_proj, cudaFuncAttributeMaxDynamicSharedMemorySize, GEMM_SMEM);
    cudaFuncSetAttribute(attn_cp,  cudaFuncAttributeMaxDynamicSharedMemorySize, ATTN_SMEM);

    dim3 gproj(D_/128, MROWS/256, 3);   // (8, 16, 3) = 384 CTAs
    proj_qkv<<<gproj, 256, GEMM_SMEM>>>(Q, K, V, Wq, Wk, Wv, bq, bk, bv, gq, gk, gv);

    dim3 ga_grid(S_/256, B_*H_);        // (8, 32) = 256 CTAs
    attn_cp<<<ga_grid, 256, ATTN_SMEM>>>();

    dim3 gout(D_/128, MROWS/256);       // (8, 16) = 128 CTAs
    out_proj<<<gout, 256, GEMM_SMEM>>>(ga, Wo, bo, out);
}

// round 8
// speedup vs baseline: 2.0866x; 1.0309x over previous
#include <cuda_runtime.h>
#include <math.h>
#include <stdint.h>

#define H_  16
#define HD_ 64
#define D_  1024
#define B_  2
#define S_  2048
#define MROWS (B_*S_)   // 4096

// q/k/v stored PRE-ROUNDED to tf32 (q pre-scaled by 0.125) in [B,H,S,HD]
__device__ float g_q[(size_t)B_*H_*S_*HD_];
__device__ float g_k[(size_t)B_*H_*S_*HD_];
__device__ float g_v[(size_t)B_*H_*S_*HD_];
__device__ float g_att[(size_t)MROWS*D_];

// ---------------------------------------------------------------------------
__device__ __forceinline__ uint32_t f2tf(float f) {
    uint32_t r; asm("cvt.rna.tf32.f32 %0, %1;" : "=r"(r) : "f"(f)); return r;
}
__device__ __forceinline__ float f2tff(float f) { return __uint_as_float(f2tf(f)); }

__device__ __forceinline__ void mma8(float* c,
    uint32_t a0, uint32_t a1, uint32_t a2, uint32_t a3,
    uint32_t b0, uint32_t b1)
{
    asm volatile(
        "mma.sync.aligned.m16n8k8.row.col.f32.tf32.tf32.f32 "
        "{%0,%1,%2,%3}, {%4,%5,%6,%7}, {%8,%9}, {%0,%1,%2,%3};"
        : "+f"(c[0]), "+f"(c[1]), "+f"(c[2]), "+f"(c[3])
        : "r"(a0), "r"(a1), "r"(a2), "r"(a3), "r"(b0), "r"(b1));
}

__device__ __forceinline__ uint32_t smem_u32(const void* p) {
    uint32_t a;
    asm("{ .reg .u64 t; cvta.to.shared.u64 t, %1; cvt.u32.u64 %0, t; }"
        : "=r"(a) : "l"(p));
    return a;
}

#define CP16(dst, src) \
    asm volatile("cp.async.cg.shared.global [%0], [%1], 16;" \
        :: "r"(dst), "l"(src) : "memory")
#define CP_COMMIT() asm volatile("cp.async.commit_group;" ::: "memory")
#define CP_WAIT1()  asm volatile("cp.async.wait_group 1;" ::: "memory")
#define CP_WAIT2()  asm volatile("cp.async.wait_group 2;" ::: "memory")

// ---------------------------------------------------------------------------
// GEMM: out[m][n] = sum_k A[m*1024+k] * W[n*1024+k] + bias[n]
// CTA 128x128, K chunks of 32; 8 warps (2m x 4n), warp tile 64x32 (regs<=128,
// 2 CTAs/SM). 3-stage cp.async ring, ONE barrier per iter, prefetch BEFORE
// compute (stage (it+2)%3 is free once the barrier at top of it has passed).
// mode 1: store f2tff((c+bias)*oscale) scattered to [B,H,S,HD]; mode 0 raw.
// smem stage: A 128x36 + B 128x36 = 36864 B; x3 = 110592.
// ---------------------------------------------------------------------------
#define GS_A    18432
#define GS_STG  36864
#define GEMM_SMEM (3*GS_STG)   // 110592

__device__ __forceinline__ void gemm_cp_body(
    const float* __restrict__ A, const float* __restrict__ W,
    const float* __restrict__ bias, float* __restrict__ out,
    int mode, float oscale, int bm, int bn, char* smc)
{
    const int tid = threadIdx.x;
    const int wid = tid >> 5, lane = tid & 31;
    const int g = lane >> 2, tig = lane & 3;
    const int wm = (wid & 1) * 64;
    const int wn = (wid >> 1) * 32;
    const uint32_t sbase = smem_u32(smc);

    // loaders: row = tid>>1, half (tid&1)*16 (4 x 16B each for A and B)
    const int row = tid >> 1, half = (tid & 1) * 16;
    const float* gA = A + (size_t)(bm + row) * D_ + half;
    const float* gB = W + (size_t)(bn + row) * D_ + half;
    const uint32_t uA = sbase + (uint32_t)(row*36 + half) * 4;
    const uint32_t uB = uA + GS_A;

    float c[4][4][4] = {};

    // prologue: chunks 0,1 -> stages 0,1
    #pragma unroll
    for (int st = 0; st < 2; st++) {
        #pragma unroll
        for (int j = 0; j < 4; j++) {
            CP16(uA + st*GS_STG + j*16, gA + st*32 + j*4);
            CP16(uB + st*GS_STG + j*16, gB + st*32 + j*4);
        }
        CP_COMMIT();
    }

    for (int it = 0; it < 32; it++) {
        CP_WAIT1();
        __syncthreads();
        // prefetch chunk it+2 into stage (it+2)%3 (= stage of chunk it-1,
        // fully consumed before the barrier above)
        if (it + 2 < 32) {
            const int ns = (it + 2) % 3;
            #pragma unroll
            for (int j = 0; j < 4; j++) {
                CP16(uA + ns*GS_STG + j*16, gA + (it+2)*32 + j*4);
                CP16(uB + ns*GS_STG + j*16, gB + (it+2)*32 + j*4);
            }
        }
        CP_COMMIT();

        const int cs = it % 3;
        const float* Ac = (const float*)(smc + cs*GS_STG);
        const float* Bc = (const float*)(smc + cs*GS_STG + GS_A);
        #pragma unroll
        for (int ks = 0; ks < 4; ks++) {
            uint32_t a[4][4], b[4][2];
            #pragma unroll
            for (int mt = 0; mt < 4; mt++) {
                int r = wm + mt*16;
                a[mt][0] = f2tf(Ac[(r+g  )*36 + ks*8 + tig    ]);
                a[mt][1] = f2tf(Ac[(r+g+8)*36 + ks*8 + tig    ]);
                a[mt][2] = f2tf(Ac[(r+g  )*36 + ks*8 + tig + 4]);
                a[mt][3] = f2tf(Ac[(r+g+8)*36 + ks*8 + tig + 4]);
            }
            #pragma unroll
            for (int nt = 0; nt < 4; nt++) {
                int n = wn + nt*8;
                b[nt][0] = f2tf(Bc[(n+g)*36 + ks*8 + tig    ]);
                b[nt][1] = f2tf(Bc[(n+g)*36 + ks*8 + tig + 4]);
            }
            #pragma unroll
            for (int mt = 0; mt < 4; mt++)
                #pragma unroll
                for (int nt = 0; nt < 4; nt++)
                    mma8(c[mt][nt], a[mt][0], a[mt][1], a[mt][2], a[mt][3],
                         b[nt][0], b[nt][1]);
        }
    }

    #pragma unroll
    for (int mt = 0; mt < 4; mt++) {
        #pragma unroll
        for (int p = 0; p < 2; p++) {
            int m = bm + wm + mt*16 + g + p*8;
            #pragma unroll
            for (int nt = 0; nt < 4; nt++) {
                int col = bn + wn + nt*8 + tig*2;
                float2 v;
                v.x = c[mt][nt][p*2+0] + bias[col];
                v.y = c[mt][nt][p*2+1] + bias[col+1];
                if (mode) {
                    v.x = f2tff(v.x * oscale);
                    v.y = f2tff(v.y * oscale);
                    int b_ = m >> 11, s = m & 2047;
                    int hh = col >> 6, e = col & 63;
                    *(float2*)&out[(((size_t)(b_*H_ + hh)*S_ + s))*HD_ + e] = v;
                } else {
                    *(float2*)&out[(size_t)m * D_ + col] = v;
                }
            }
        }
    }
}

__global__ void __launch_bounds__(256, 2) proj_qkv(
    const float* __restrict__ Q, const float* __restrict__ K, const float* __restrict__ V,
    const float* __restrict__ Wq, const float* __restrict__ Wk, const float* __restrict__ Wv,
    const float* __restrict__ bq, const float* __restrict__ bk, const float* __restrict__ bv,
    float* __restrict__ oq, float* __restrict__ ok, float* __restrict__ ov)
{
    extern __shared__ char smc[];
    const float *A, *W, *bias; float* out; float sc;
    if (blockIdx.z == 0)      { A = Q; W = Wq; bias = bq; out = oq; sc = 0.125f; }
    else if (blockIdx.z == 1) { A = K; W = Wk; bias = bk; out = ok; sc = 1.0f; }
    else                      { A = V; W = Wv; bias = bv; out = ov; sc = 1.0f; }
    gemm_cp_body(A, W, bias, out, 1, sc, blockIdx.y*128, blockIdx.x*128, smc);
}

__global__ void __launch_bounds__(256, 2) out_proj(
    const float* __restrict__ A, const float* __restrict__ W,
    const float* __restrict__ bias, float* __restrict__ out)
{
    extern __shared__ char smc[];
    gemm_cp_body(A, W, bias, out, 0, 1.0f, blockIdx.y*128, blockIdx.x*128, smc);
}

// ---------------------------------------------------------------------------
// Flash attention: 256 thr / 8 warps, 32 q-rows per warp (256 q-rows/CTA),
// K/V 64-row blocks, 3-stage cp.async ring, ONE barrier per iter, prefetch
// before compute. P kept in registers via shuffles. Q/K/V already tf32.
// smem: Qs 256x68 (69632 B) + 3 stages of (K 64x68 + V 64x72) (35840 each).
// ---------------------------------------------------------------------------
#define KV_STG   35840         // 17408 K + 18432 V
#define ATTN_SMEM (69632 + 3*KV_STG)   // 177152
#define NITER (S_/64)

__global__ void __launch_bounds__(256) attn_cp()
{
    extern __shared__ char smc[];
    const int bh = blockIdx.y;
    const int b  = bh >> 4, h = bh & 15;
    const int q0 = blockIdx.x * 256;
    const float* qp = g_q + (size_t)bh * S_ * HD_;
    const float* kp = g_k + (size_t)bh * S_ * HD_;
    const float* vp = g_v + (size_t)bh * S_ * HD_;

    const int tid = threadIdx.x;
    const int wid = tid >> 5, lane = tid & 31;
    const int g = lane >> 2, tig = lane & 3;
    const int wrow = wid * 32;
    const uint32_t sbase = smem_u32(smc);

    // Q: one-time cp.async, one row (64 floats) per thread
    {
        uint32_t dst = sbase + (uint32_t)(tid * 68) * 4;
        const float* src = qp + (size_t)(q0 + tid) * HD_;
        #pragma unroll
        for (int j = 0; j < 16; j++) CP16(dst + j*16, src + j*4);
    }
    // K/V loaders
    const int kvrow = tid >> 2, kvq = (tid & 3) * 16;
    const uint32_t ukb = sbase + 69632 + (uint32_t)(kvrow*68 + kvq)*4;
    const uint32_t uvb = sbase + 69632 + 17408 + (uint32_t)(kvrow*72 + kvq)*4;
    #pragma unroll
    for (int st = 0; st < 2; st++) {
        const float* sk = kp + (size_t)(st*64 + kvrow) * HD_ + kvq;
        const float* sv = vp + (size_t)(st*64 + kvrow) * HD_ + kvq;
        #pragma unroll
        for (int j = 0; j < 4; j++) CP16(ukb + st*KV_STG + j*16, sk + j*4);
        #pragma unroll
        for (int j = 0; j < 4; j++) CP16(uvb + st*KV_STG + j*16, sv + j*4);
        CP_COMMIT();
    }

    const float* Qs = (const float*)smc;
    float mx[2][2], lsum[2][2];
    #pragma unroll
    for (int mt = 0; mt < 2; mt++) {
        mx[mt][0] = mx[mt][1] = -1e30f;
        lsum[mt][0] = lsum[mt][1] = 0.f;
    }
    float acc[2][8][4] = {};
    const int src0 = (lane & ~3) | (tig >> 1);
    const int src2 = src0 + 2;
    const bool podd = (tig & 1);

    for (int it = 0; it < NITER; it++) {
        CP_WAIT1();
        __syncthreads();
        // prefetch KV chunk it+2 into stage (it+2)%3 (free after barrier)
        if (it + 2 < NITER) {
            const int ns = (it + 2) % 3;
            const float* sk = kp + (size_t)((it+2)*64 + kvrow) * HD_ + kvq;
            const float* sv = vp + (size_t)((it+2)*64 + kvrow) * HD_ + kvq;
            #pragma unroll
            for (int j = 0; j < 4; j++) CP16(ukb + ns*KV_STG + j*16, sk + j*4);
            #pragma unroll
            for (int j = 0; j < 4; j++) CP16(uvb + ns*KV_STG + j*16, sv + j*4);
        }
        CP_COMMIT();

        const int cs = it % 3;
        const float* Kc = (const float*)(smc + 69632 + cs*KV_STG);
        const float* Vc = (const float*)(smc + 69632 + cs*KV_STG + 17408);

        // S = Q K^T : warp tile 32 x 64
        float s[2][8][4] = {};
        #pragma unroll
        for (int ksd = 0; ksd < 8; ksd++) {
            uint32_t a[2][4];
            #pragma unroll
            for (int mt = 0; mt < 2; mt++) {
                int r = wrow + mt*16;
                a[mt][0] = __float_as_uint(Qs[(r+g  )*68 + ksd*8 + tig    ]);
                a[mt][1] = __float_as_uint(Qs[(r+g+8)*68 + ksd*8 + tig    ]);
                a[mt][2] = __float_as_uint(Qs[(r+g  )*68 + ksd*8 + tig + 4]);
                a[mt][3] = __float_as_uint(Qs[(r+g+8)*68 + ksd*8 + tig + 4]);
            }
            #pragma unroll
            for (int nt = 0; nt < 8; nt++) {
                uint32_t b0 = __float_as_uint(Kc[(nt*8+g)*68 + ksd*8 + tig    ]);
                uint32_t b1 = __float_as_uint(Kc[(nt*8+g)*68 + ksd*8 + tig + 4]);
                mma8(s[0][nt], a[0][0], a[0][1], a[0][2], a[0][3], b0, b1);
                mma8(s[1][nt], a[1][0], a[1][1], a[1][2], a[1][3], b0, b1);
            }
        }

        // online softmax per m-tile; p overwrites s
        #pragma unroll
        for (int mt = 0; mt < 2; mt++) {
            float rm0 = -1e30f, rm1 = -1e30f;
            #pragma unroll
            for (int nt = 0; nt < 8; nt++) {
                rm0 = fmaxf(rm0, fmaxf(s[mt][nt][0], s[mt][nt][1]));
                rm1 = fmaxf(rm1, fmaxf(s[mt][nt][2], s[mt][nt][3]));
            }
            rm0 = fmaxf(rm0, __shfl_xor_sync(0xffffffffu, rm0, 1));
            rm0 = fmaxf(rm0, __shfl_xor_sync(0xffffffffu, rm0, 2));
            rm1 = fmaxf(rm1, __shfl_xor_sync(0xffffffffu, rm1, 1));
            rm1 = fmaxf(rm1, __shfl_xor_sync(0xffffffffu, rm1, 2));

            float nm0 = fmaxf(mx[mt][0], rm0), nm1 = fmaxf(mx[mt][1], rm1);
            float al0 = __expf(mx[mt][0] - nm0), al1 = __expf(mx[mt][1] - nm1);
            mx[mt][0] = nm0; mx[mt][1] = nm1;

            float sum0 = 0.f, sum1 = 0.f;
            #pragma unroll
            for (int nt = 0; nt < 8; nt++) {
                float p0 = __expf(s[mt][nt][0] - nm0);
                float p1 = __expf(s[mt][nt][1] - nm0);
                float p2 = __expf(s[mt][nt][2] - nm1);
                float p3 = __expf(s[mt][nt][3] - nm1);
                sum0 += p0 + p1; sum1 += p2 + p3;
                s[mt][nt][0] = p0; s[mt][nt][1] = p1;
                s[mt][nt][2] = p2; s[mt][nt][3] = p3;
            }
            sum0 += __shfl_xor_sync(0xffffffffu, sum0, 1);
            sum0 += __shfl_xor_sync(0xffffffffu, sum0, 2);
            sum1 += __shfl_xor_sync(0xffffffffu, sum1, 1);
            sum1 += __shfl_xor_sync(0xffffffffu, sum1, 2);
            lsum[mt][0] = lsum[mt][0] * al0 + sum0;
            lsum[mt][1] = lsum[mt][1] * al1 + sum1;

            #pragma unroll
            for (int nt = 0; nt < 8; nt++) {
                acc[mt][nt][0] *= al0; acc[mt][nt][1] *= al0;
                acc[mt][nt][2] *= al1; acc[mt][nt][3] *= al1;
            }
        }

        // acc += P * V; P A-frags via shuffle from C-frags s[mt][ksd][*]
        #pragma unroll
        for (int ksd = 0; ksd < 8; ksd++) {
            uint32_t pa[2][4];
            #pragma unroll
            for (int mt = 0; mt < 2; mt++) {
                float v00 = __shfl_sync(0xffffffffu, s[mt][ksd][0], src0);
                float v01 = __shfl_sync(0xffffffffu, s[mt][ksd][1], src0);
                float v10 = __shfl_sync(0xffffffffu, s[mt][ksd][2], src0);
                float v11 = __shfl_sync(0xffffffffu, s[mt][ksd][3], src0);
                float w00 = __shfl_sync(0xffffffffu, s[mt][ksd][0], src2);
                float w01 = __shfl_sync(0xffffffffu, s[mt][ksd][1], src2);
                float w10 = __shfl_sync(0xffffffffu, s[mt][ksd][2], src2);
                float w11 = __shfl_sync(0xffffffffu, s[mt][ksd][3], src2);
                pa[mt][0] = f2tf(podd ? v01 : v00);
                pa[mt][1] = f2tf(podd ? v11 : v10);
                pa[mt][2] = f2tf(podd ? w01 : w00);
                pa[mt][3] = f2tf(podd ? w11 : w10);
            }
            #pragma unroll
            for (int nt = 0; nt < 8; nt++) {
                uint32_t b0 = __float_as_uint(Vc[(ksd*8+tig  )*72 + nt*8 + g]);
                uint32_t b1 = __float_as_uint(Vc[(ksd*8+tig+4)*72 + nt*8 + g]);
                mma8(acc[0][nt], pa[0][0], pa[0][1], pa[0][2], pa[0][3], b0, b1);
                mma8(acc[1][nt], pa[1][0], pa[1][1], pa[1][2], pa[1][3], b0, b1);
            }
        }
    }

    // epilogue: normalize, store concat layout
    #pragma unroll
    for (int mt = 0; mt < 2; mt++) {
        float inv0 = 1.0f / lsum[mt][0], inv1 = 1.0f / lsum[mt][1];
        int r0 = q0 + wrow + mt*16 + g;
        int r1 = r0 + 8;
        #pragma unroll
        for (int nt = 0; nt < 8; nt++) {
            int col = h*64 + nt*8 + tig*2;
            float2 v0, v1;
            v0.x = acc[mt][nt][0]*inv0; v0.y = acc[mt][nt][1]*inv0;
            v1.x = acc[mt][nt][2]*inv1; v1.y = acc[mt][nt][3]*inv1;
            *(float2*)&g_att[(size_t)(b*S_ + r0)*D_ + col] = v0;
            *(float2*)&g_att[(size_t)(b*S_ + r1)*D_ + col] = v1;
        }
    }
}

// ---------------------------------------------------------------------------
extern "C" void kernel_launch(void* const* d_in, const int* in_sizes, int n_in,
                              void* d_out, int out_size)
{
    const float* V  = (const float*)d_in[0];
    const float* K  = (const float*)d_in[1];
    const float* Q  = (const float*)d_in[2];
    const float* Wv = (const float*)d_in[3];
    const float* bv = (const float*)d_in[4];
    const float* Wk = (const float*)d_in[5];
    const float* bk = (const float*)d_in[6];
    const float* Wq = (const float*)d_in[7];
    const float* bq = (const float*)d_in[8];
    const float* Wo = (const float*)d_in[9];
    const float* bo = (const float*)d_in[10];
    float* out = (float*)d_out;

    (void)in_sizes; (void)n_in; (void)out_size;

    float* gq; cudaGetSymbolAddress((void**)&gq, g_q);
    float* gk; cudaGetSymbolAddress((void**)&gk, g_k);
    float* gv; cudaGetSymbolAddress((void**)&gv, g_v);
    float* ga; cudaGetSymbolAddress((void**)&ga, g_att);

    cudaFuncSetAttribute(proj_qkv, cudaFuncAttributeMaxDynamicSharedMemorySize, GEMM_SMEM);
    cudaFuncSetAttribute(out_proj, cudaFuncAttributeMaxDynamicSharedMemorySize, GEMM_SMEM);
    cudaFuncSetAttribute(attn_cp,  cudaFuncAttributeMaxDynamicSharedMemorySize, ATTN_SMEM);

    dim3 gproj(D_/128, MROWS/128, 3);   // (8, 32, 3) = 768 CTAs
    proj_qkv<<<gproj, 256, GEMM_SMEM>>>(Q, K, V, Wq, Wk, Wv, bq, bk, bv, gq, gk, gv);

    dim3 ga_grid(S_/256, B_*H_);        // (8, 32) = 256 CTAs
    attn_cp<<<ga_grid, 256, ATTN_SMEM>>>();

    dim3 gout(D_/128, MROWS/128);       // (8, 32) = 256 CTAs
    out_proj<<<gout, 256, GEMM_SMEM>>>(ga, Wo, bo, out);
}

// round 9
// speedup vs baseline: 3.7137x; 1.7798x over previous
#include <cuda_runtime.h>
#include <cuda_fp16.h>
#include <math.h>
#include <stdint.h>

#define H_  16
#define HD_ 64
#define D_  1024
#define B_  2
#define S_  2048
#define MROWS (B_*S_)   // 4096

// fp16 scratch
__device__ __half g_inq[(size_t)MROWS*D_];     // Q input, half
__device__ __half g_ink[(size_t)MROWS*D_];     // K input, half
__device__ __half g_inv[(size_t)MROWS*D_];     // V input, half
__device__ __half g_wq[(size_t)D_*D_];
__device__ __half g_wk[(size_t)D_*D_];
__device__ __half g_wv[(size_t)D_*D_];
__device__ __half g_wo[(size_t)D_*D_];
__device__ __half g_qh[(size_t)B_*H_*S_*HD_];  // q proj, [B,H,S,HD], pre-scaled 0.125
__device__ __half g_kh[(size_t)B_*H_*S_*HD_];  // k proj, [B,H,S,HD]
__device__ __half g_vt[(size_t)B_*H_*HD_*S_];  // v proj, TRANSPOSED [B,H,HD,S]
__device__ __half g_atth[(size_t)MROWS*D_];    // attention out, concat layout, half

// ---------------------------------------------------------------------------
__device__ __forceinline__ void mma16(float* c,
    uint32_t a0, uint32_t a1, uint32_t a2, uint32_t a3,
    uint32_t b0, uint32_t b1)
{
    asm volatile(
        "mma.sync.aligned.m16n8k16.row.col.f32.f16.f16.f32 "
        "{%0,%1,%2,%3}, {%4,%5,%6,%7}, {%8,%9}, {%0,%1,%2,%3};"
        : "+f"(c[0]), "+f"(c[1]), "+f"(c[2]), "+f"(c[3])
        : "r"(a0), "r"(a1), "r"(a2), "r"(a3), "r"(b0), "r"(b1));
}

__device__ __forceinline__ uint32_t smem_u32(const void* p) {
    uint32_t a;
    asm("{ .reg .u64 t; cvta.to.shared.u64 t, %1; cvt.u32.u64 %0, t; }"
        : "=r"(a) : "l"(p));
    return a;
}
__device__ __forceinline__ uint32_t h2pack(float x, float y) {
    __half2 h = __floats2half2_rn(x, y);
    return *(uint32_t*)&h;
}

#define CP16(dst, src) \
    asm volatile("cp.async.cg.shared.global [%0], [%1], 16;" \
        :: "r"(dst), "l"(src) : "memory")
#define CP_COMMIT() asm volatile("cp.async.commit_group;" ::: "memory")
#define CP_WAIT1()  asm volatile("cp.async.wait_group 1;" ::: "memory")

// ---------------------------------------------------------------------------
// fp32 -> fp16 streaming convert (8 elems/thread)
// ---------------------------------------------------------------------------
__global__ void __launch_bounds__(256) cvt_h(const float* __restrict__ src,
                                             __half* __restrict__ dst, int n8)
{
    int i = blockIdx.x * 256 + threadIdx.x;
    if (i < n8) {
        float4 f0 = ((const float4*)src)[i*2];
        float4 f1 = ((const float4*)src)[i*2+1];
        uint4 o;
        o.x = h2pack(f0.x, f0.y);
        o.y = h2pack(f0.z, f0.w);
        o.z = h2pack(f1.x, f1.y);
        o.w = h2pack(f1.z, f1.w);
        ((uint4*)dst)[i] = o;
    }
}

// ---------------------------------------------------------------------------
// fp16 GEMM: out[m][n] = sum_k A[m*1024+k] * W[n*1024+k] + bias[n]
// CTA 128x128, K chunks of 64 halves; 8 warps (2m x 4n), warp 64x32.
// 3-stage cp.async ring, one barrier/iter, prefetch before compute.
// smem stage: A 128x72 halves (18432 B) + B same = 36864 B; x3 = 110592.
// mode 0: fp32 row-major. mode 1: half scatter [B,H,S,HD] (*oscale).
// mode 2: half scatter transposed [B,H,HD,S].
// ---------------------------------------------------------------------------
#define GS_A    18432
#define GS_STG  36864
#define GEMM_SMEM (3*GS_STG)

__device__ __forceinline__ void gemm_h_body(
    const __half* __restrict__ A, const __half* __restrict__ W,
    const float* __restrict__ bias, void* __restrict__ out,
    int mode, float oscale, int bm, int bn, char* smc)
{
    const int tid = threadIdx.x;
    const int wid = tid >> 5, lane = tid & 31;
    const int g = lane >> 2, tig = lane & 3;
    const int wm = (wid & 1) * 64;
    const int wn = (wid >> 1) * 32;
    const uint32_t sbase = smem_u32(smc);

    // loaders: row = tid>>1, seg (tid&1)*32 halves (64B = 4 CP16 each)
    const int row = tid >> 1, seg = (tid & 1) * 32;
    const __half* gA = A + (size_t)(bm + row) * D_ + seg;
    const __half* gB = W + (size_t)(bn + row) * D_ + seg;
    const uint32_t uA = sbase + (uint32_t)(row*72 + seg) * 2;
    const uint32_t uB = uA + GS_A;

    float c[4][4][4] = {};

    #pragma unroll
    for (int st = 0; st < 2; st++) {
        #pragma unroll
        for (int j = 0; j < 4; j++) {
            CP16(uA + st*GS_STG + j*16, gA + st*64 + j*8);
            CP16(uB + st*GS_STG + j*16, gB + st*64 + j*8);
        }
        CP_COMMIT();
    }

    const int NCH = D_ / 64;   // 16
    for (int it = 0; it < NCH; it++) {
        CP_WAIT1();
        __syncthreads();
        if (it + 2 < NCH) {
            const int ns = (it + 2) % 3;
            #pragma unroll
            for (int j = 0; j < 4; j++) {
                CP16(uA + ns*GS_STG + j*16, gA + (it+2)*64 + j*8);
                CP16(uB + ns*GS_STG + j*16, gB + (it+2)*64 + j*8);
            }
        }
        CP_COMMIT();

        const int cs = it % 3;
        const __half* Ac = (const __half*)(smc + cs*GS_STG);
        const __half* Bc = (const __half*)(smc + cs*GS_STG + GS_A);
        #pragma unroll
        for (int kt = 0; kt < 4; kt++) {
            uint32_t a[4][4], b[4][2];
            #pragma unroll
            for (int mt = 0; mt < 4; mt++) {
                int r = wm + mt*16;
                a[mt][0] = *(const uint32_t*)&Ac[(r+g  )*72 + kt*16 + 2*tig    ];
                a[mt][1] = *(const uint32_t*)&Ac[(r+g+8)*72 + kt*16 + 2*tig    ];
                a[mt][2] = *(const uint32_t*)&Ac[(r+g  )*72 + kt*16 + 2*tig + 8];
                a[mt][3] = *(const uint32_t*)&Ac[(r+g+8)*72 + kt*16 + 2*tig + 8];
            }
            #pragma unroll
            for (int nt = 0; nt < 4; nt++) {
                int n = wn + nt*8 + g;
                b[nt][0] = *(const uint32_t*)&Bc[n*72 + kt*16 + 2*tig    ];
                b[nt][1] = *(const uint32_t*)&Bc[n*72 + kt*16 + 2*tig + 8];
            }
            #pragma unroll
            for (int mt = 0; mt < 4; mt++)
                #pragma unroll
                for (int nt = 0; nt < 4; nt++)
                    mma16(c[mt][nt], a[mt][0], a[mt][1], a[mt][2], a[mt][3],
                          b[nt][0], b[nt][1]);
        }
    }

    #pragma unroll
    for (int mt = 0; mt < 4; mt++) {
        #pragma unroll
        for (int p = 0; p < 2; p++) {
            int m = bm + wm + mt*16 + g + p*8;
            #pragma unroll
            for (int nt = 0; nt < 4; nt++) {
                int col = bn + wn + nt*8 + tig*2;
                float vx = c[mt][nt][p*2+0] + bias[col];
                float vy = c[mt][nt][p*2+1] + bias[col+1];
                if (mode == 0) {
                    float2 v; v.x = vx; v.y = vy;
                    *(float2*)&((float*)out)[(size_t)m * D_ + col] = v;
                } else if (mode == 1) {
                    int b_ = m >> 11, s = m & 2047;
                    int hh = col >> 6, e = col & 63;
                    __half2 hv = __floats2half2_rn(vx * oscale, vy * oscale);
                    *(__half2*)&((__half*)out)[(((size_t)(b_*H_ + hh)*S_ + s))*HD_ + e] = hv;
                } else {
                    // transposed scatter [B,H,HD,S]
                    int b_ = m >> 11, s = m & 2047;
                    int hh = col >> 6, e = col & 63;
                    __half* dst = (__half*)out + ((size_t)(b_*H_ + hh)*HD_)*S_;
                    dst[(size_t)(e  )*S_ + s] = __float2half_rn(vx);
                    dst[(size_t)(e+1)*S_ + s] = __float2half_rn(vy);
                }
            }
        }
    }
}

__global__ void __launch_bounds__(256, 2) proj_qkv(
    const float* __restrict__ bq, const float* __restrict__ bk, const float* __restrict__ bv)
{
    extern __shared__ char smc[];
    const __half *A, *W; const float* bias; void* out; float sc; int mode;
    if (blockIdx.z == 0)      { A = g_inq; W = g_wq; bias = bq; out = g_qh; sc = 0.125f; mode = 1; }
    else if (blockIdx.z == 1) { A = g_ink; W = g_wk; bias = bk; out = g_kh; sc = 1.0f;   mode = 1; }
    else                      { A = g_inv; W = g_wv; bias = bv; out = g_vt; sc = 1.0f;   mode = 2; }
    gemm_h_body(A, W, bias, out, mode, sc, blockIdx.y*128, blockIdx.x*128, smc);
}

__global__ void __launch_bounds__(256, 2) out_proj(
    const float* __restrict__ bias, float* __restrict__ out)
{
    extern __shared__ char smc[];
    gemm_h_body(g_atth, g_wo, bias, out, 0, 1.0f, blockIdx.y*128, blockIdx.x*128, smc);
}

// ---------------------------------------------------------------------------
// fp16 flash attention: 256 thr / 8 warps, 16 q-rows per warp (128/CTA),
// K/V 64-row blocks, 3-stage cp.async ring, one barrier/iter.
// Q [row][hd] halves; K [kv][hd] halves; V transposed [hd][kv] halves.
// P: C-frag -> A-frag is thread-local half2 packing (no shuffles).
// smem: Qs 128x72 h (18432) + 3 stages of (K 64x72 + V 64x72) (18432 each).
// ---------------------------------------------------------------------------
#define KV_STG   18432
#define ATTN_SMEM (18432 + 3*KV_STG)   // 73728
#define NITER (S_/64)

__global__ void __launch_bounds__(256, 2) attn_h()
{
    extern __shared__ char smc[];
    const int bh = blockIdx.y;
    const int b  = bh >> 4, h = bh & 15;
    const int q0 = blockIdx.x * 128;
    const __half* qp  = g_qh + (size_t)bh * S_ * HD_;
    const __half* kp  = g_kh + (size_t)bh * S_ * HD_;
    const __half* vtp = g_vt + (size_t)bh * HD_ * S_;   // [hd][S]

    const int tid = threadIdx.x;
    const int wid = tid >> 5, lane = tid & 31;
    const int g = lane >> 2, tig = lane & 3;
    const int wrow = wid * 16;
    const uint32_t sbase = smem_u32(smc);

    // Q: 128 rows x 64 halves; row = tid>>1, seg (tid&1)*32 halves (4 CP16)
    {
        int row = tid >> 1, seg = (tid & 1) * 32;
        uint32_t dst = sbase + (uint32_t)(row*72 + seg) * 2;
        const __half* src = qp + (size_t)(q0 + row) * HD_ + seg;
        #pragma unroll
        for (int j = 0; j < 4; j++) CP16(dst + j*16, src + j*8);
    }
    // K/V loaders: row = tid>>2 (kv row for K, hd row for V), seg (tid&3)*16 halves
    const int kvr = tid >> 2, kvs = (tid & 3) * 16;
    const uint32_t ukb = sbase + 18432 + (uint32_t)(kvr*72 + kvs) * 2;
    const uint32_t uvb = ukb + 9216;
    #pragma unroll
    for (int st = 0; st < 2; st++) {
        const __half* sk = kp  + (size_t)(st*64 + kvr) * HD_ + kvs;
        const __half* sv = vtp + (size_t)kvr * S_ + st*64 + kvs;
        CP16(ukb + st*KV_STG,      sk);
        CP16(ukb + st*KV_STG + 16, sk + 8);
        CP16(uvb + st*KV_STG,      sv);
        CP16(uvb + st*KV_STG + 16, sv + 8);
        CP_COMMIT();
    }

    const __half* Qs = (const __half*)smc;
    float mx0 = -1e30f, mx1 = -1e30f, l0 = 0.f, l1 = 0.f;
    float acc[8][4] = {};

    for (int it = 0; it < NITER; it++) {
        CP_WAIT1();
        __syncthreads();
        if (it + 2 < NITER) {
            const int ns = (it + 2) % 3;
            const __half* sk = kp  + (size_t)((it+2)*64 + kvr) * HD_ + kvs;
            const __half* sv = vtp + (size_t)kvr * S_ + (it+2)*64 + kvs;
            CP16(ukb + ns*KV_STG,      sk);
            CP16(ukb + ns*KV_STG + 16, sk + 8);
            CP16(uvb + ns*KV_STG,      sv);
            CP16(uvb + ns*KV_STG + 16, sv + 8);
        }
        CP_COMMIT();

        const int cs = it % 3;
        const __half* Kc = (const __half*)(smc + 18432 + cs*KV_STG);
        const __half* Vc = (const __half*)(smc + 18432 + cs*KV_STG + 9216);

        // S = Q K^T : warp tile 16 x 64, K=64 (4 k16 steps)
        float s[8][4] = {};
        #pragma unroll
        for (int kt = 0; kt < 4; kt++) {
            uint32_t a0 = *(const uint32_t*)&Qs[(wrow+g  )*72 + kt*16 + 2*tig    ];
            uint32_t a1 = *(const uint32_t*)&Qs[(wrow+g+8)*72 + kt*16 + 2*tig    ];
            uint32_t a2 = *(const uint32_t*)&Qs[(wrow+g  )*72 + kt*16 + 2*tig + 8];
            uint32_t a3 = *(const uint32_t*)&Qs[(wrow+g+8)*72 + kt*16 + 2*tig + 8];
            #pragma unroll
            for (int nt = 0; nt < 8; nt++) {
                uint32_t b0 = *(const uint32_t*)&Kc[(nt*8+g)*72 + kt*16 + 2*tig    ];
                uint32_t b1 = *(const uint32_t*)&Kc[(nt*8+g)*72 + kt*16 + 2*tig + 8];
                mma16(s[nt], a0, a1, a2, a3, b0, b1);
            }
        }

        // online softmax (rows wrow+g, wrow+g+8)
        float rm0 = -1e30f, rm1 = -1e30f;
        #pragma unroll
        for (int nt = 0; nt < 8; nt++) {
            rm0 = fmaxf(rm0, fmaxf(s[nt][0], s[nt][1]));
            rm1 = fmaxf(rm1, fmaxf(s[nt][2], s[nt][3]));
        }
        rm0 = fmaxf(rm0, __shfl_xor_sync(0xffffffffu, rm0, 1));
        rm0 = fmaxf(rm0, __shfl_xor_sync(0xffffffffu, rm0, 2));
        rm1 = fmaxf(rm1, __shfl_xor_sync(0xffffffffu, rm1, 1));
        rm1 = fmaxf(rm1, __shfl_xor_sync(0xffffffffu, rm1, 2));

        float nm0 = fmaxf(mx0, rm0), nm1 = fmaxf(mx1, rm1);
        float al0 = __expf(mx0 - nm0), al1 = __expf(mx1 - nm1);
        mx0 = nm0; mx1 = nm1;

        float sum0 = 0.f, sum1 = 0.f;
        #pragma unroll
        for (int nt = 0; nt < 8; nt++) {
            float p0 = __expf(s[nt][0] - nm0);
            float p1 = __expf(s[nt][1] - nm0);
            float p2 = __expf(s[nt][2] - nm1);
            float p3 = __expf(s[nt][3] - nm1);
            sum0 += p0 + p1; sum1 += p2 + p3;
            s[nt][0] = p0; s[nt][1] = p1; s[nt][2] = p2; s[nt][3] = p3;
        }
        sum0 += __shfl_xor_sync(0xffffffffu, sum0, 1);
        sum0 += __shfl_xor_sync(0xffffffffu, sum0, 2);
        sum1 += __shfl_xor_sync(0xffffffffu, sum1, 1);
        sum1 += __shfl_xor_sync(0xffffffffu, sum1, 2);
        l0 = l0 * al0 + sum0;
        l1 = l1 * al1 + sum1;

        #pragma unroll
        for (int nt = 0; nt < 8; nt++) {
            acc[nt][0] *= al0; acc[nt][1] *= al0;
            acc[nt][2] *= al1; acc[nt][3] *= al1;
        }

        // acc += P * V : P A-frags are thread-local packs of the C-frags
        #pragma unroll
        for (int kt = 0; kt < 4; kt++) {
            uint32_t pa0 = h2pack(s[2*kt  ][0], s[2*kt  ][1]);
            uint32_t pa1 = h2pack(s[2*kt  ][2], s[2*kt  ][3]);
            uint32_t pa2 = h2pack(s[2*kt+1][0], s[2*kt+1][1]);
            uint32_t pa3 = h2pack(s[2*kt+1][2], s[2*kt+1][3]);
            #pragma unroll
            for (int nt = 0; nt < 8; nt++) {
                uint32_t b0 = *(const uint32_t*)&Vc[(nt*8+g)*72 + kt*16 + 2*tig    ];
                uint32_t b1 = *(const uint32_t*)&Vc[(nt*8+g)*72 + kt*16 + 2*tig + 8];
                mma16(acc[nt], pa0, pa1, pa2, pa3, b0, b1);
            }
        }
    }

    // epilogue: normalize, store half concat layout
    float inv0 = 1.0f / l0, inv1 = 1.0f / l1;
    int r0 = q0 + wrow + g;
    int r1 = r0 + 8;
    #pragma unroll
    for (int nt = 0; nt < 8; nt++) {
        int col = h*64 + nt*8 + tig*2;
        *(__half2*)&g_atth[(size_t)(b*S_ + r0)*D_ + col] =
            __floats2half2_rn(acc[nt][0]*inv0, acc[nt][1]*inv0);
        *(__half2*)&g_atth[(size_t)(b*S_ + r1)*D_ + col] =
            __floats2half2_rn(acc[nt][2]*inv1, acc[nt][3]*inv1);
    }
}

// ---------------------------------------------------------------------------
extern "C" void kernel_launch(void* const* d_in, const int* in_sizes, int n_in,
                              void* d_out, int out_size)
{
    const float* V  = (const float*)d_in[0];
    const float* K  = (const float*)d_in[1];
    const float* Q  = (const float*)d_in[2];
    const float* Wv = (const float*)d_in[3];
    const float* bv = (const float*)d_in[4];
    const float* Wk = (const float*)d_in[5];
    const float* bk = (const float*)d_in[6];
    const float* Wq = (const float*)d_in[7];
    const float* bq = (const float*)d_in[8];
    const float* Wo = (const float*)d_in[9];
    const float* bo = (const float*)d_in[10];
    float* out = (float*)d_out;

    (void)in_sizes; (void)n_in; (void)out_size;

    __half *inq, *ink, *inv, *wq, *wk, *wv, *wo;
    cudaGetSymbolAddress((void**)&inq, g_inq);
    cudaGetSymbolAddress((void**)&ink, g_ink);
    cudaGetSymbolAddress((void**)&inv, g_inv);
    cudaGetSymbolAddress((void**)&wq, g_wq);
    cudaGetSymbolAddress((void**)&wk, g_wk);
    cudaGetSymbolAddress((void**)&wv, g_wv);
    cudaGetSymbolAddress((void**)&wo, g_wo);

    const int nAct8 = MROWS * D_ / 8;   // 524288
    const int nW8   = D_ * D_ / 8;      // 131072
    cvt_h<<<nAct8/256, 256>>>(Q,  inq, nAct8);
    cvt_h<<<nAct8/256, 256>>>(K,  ink, nAct8);
    cvt_h<<<nAct8/256, 256>>>(V,  inv, nAct8);
    cvt_h<<<nW8/256,   256>>>(Wq, wq,  nW8);
    cvt_h<<<nW8/256,   256>>>(Wk, wk,  nW8);
    cvt_h<<<nW8/256,   256>>>(Wv, wv,  nW8);
    cvt_h<<<nW8/256,   256>>>(Wo, wo,  nW8);

    cudaFuncSetAttribute(proj_qkv, cudaFuncAttributeMaxDynamicSharedMemorySize, GEMM_SMEM);
    cudaFuncSetAttribute(out_proj, cudaFuncAttributeMaxDynamicSharedMemorySize, GEMM_SMEM);
    cudaFuncSetAttribute(attn_h,   cudaFuncAttributeMaxDynamicSharedMemorySize, ATTN_SMEM);

    dim3 gproj(D_/128, MROWS/128, 3);   // (8, 32, 3)
    proj_qkv<<<gproj, 256, GEMM_SMEM>>>(bq, bk, bv);

    dim3 ga_grid(S_/128, B_*H_);        // (16, 32) = 512 CTAs
    attn_h<<<ga_grid, 256, ATTN_SMEM>>>();

    dim3 gout(D_/128, MROWS/128);       // (8, 32)
    out_proj<<<gout, 256, GEMM_SMEM>>>(bo, out);
}

// round 10
// speedup vs baseline: 4.1057x; 1.1056x over previous
#include <cuda_runtime.h>
#include <cuda_fp16.h>
#include <math.h>
#include <stdint.h>

#define H_  16
#define HD_ 64
#define D_  1024
#define B_  2
#define S_  2048
#define MROWS (B_*S_)   // 4096

// fp16 scratch
__device__ __half g_inq[(size_t)MROWS*D_];
__device__ __half g_ink[(size_t)MROWS*D_];
__device__ __half g_inv[(size_t)MROWS*D_];
__device__ __half g_wq[(size_t)D_*D_];
__device__ __half g_wk[(size_t)D_*D_];
__device__ __half g_wv[(size_t)D_*D_];
__device__ __half g_wo[(size_t)D_*D_];
__device__ __half g_qh[(size_t)B_*H_*S_*HD_];  // q proj, pre-scaled 0.125
__device__ __half g_kh[(size_t)B_*H_*S_*HD_];
__device__ __half g_vt[(size_t)B_*H_*HD_*S_];  // v proj, transposed [B,H,HD,S]
__device__ __half g_atth[(size_t)MROWS*D_];    // attention out, concat, half

// ---------------------------------------------------------------------------
__device__ __forceinline__ void mma16(float* c,
    uint32_t a0, uint32_t a1, uint32_t a2, uint32_t a3,
    uint32_t b0, uint32_t b1)
{
    asm volatile(
        "mma.sync.aligned.m16n8k16.row.col.f32.f16.f16.f32 "
        "{%0,%1,%2,%3}, {%4,%5,%6,%7}, {%8,%9}, {%0,%1,%2,%3};"
        : "+f"(c[0]), "+f"(c[1]), "+f"(c[2]), "+f"(c[3])
        : "r"(a0), "r"(a1), "r"(a2), "r"(a3), "r"(b0), "r"(b1));
}

#define LDSM4(r0, r1, r2, r3, addr) \
    asm volatile("ldmatrix.sync.aligned.m8n8.x4.shared.b16 {%0,%1,%2,%3}, [%4];" \
        : "=r"(r0), "=r"(r1), "=r"(r2), "=r"(r3) : "r"(addr))

__device__ __forceinline__ uint32_t smem_u32(const void* p) {
    uint32_t a;
    asm("{ .reg .u64 t; cvta.to.shared.u64 t, %1; cvt.u32.u64 %0, t; }"
        : "=r"(a) : "l"(p));
    return a;
}
__device__ __forceinline__ uint32_t h2pack(float x, float y) {
    __half2 h = __floats2half2_rn(x, y);
    return *(uint32_t*)&h;
}

#define CP16(dst, src) \
    asm volatile("cp.async.cg.shared.global [%0], [%1], 16;" \
        :: "r"(dst), "l"(src) : "memory")
#define CP_COMMIT() asm volatile("cp.async.commit_group;" ::: "memory")
#define CP_WAIT1()  asm volatile("cp.async.wait_group 1;" ::: "memory")

// ---------------------------------------------------------------------------
// fp32 -> fp16 converts, fused: 3 activations / 4 weights via blockIdx.y
// ---------------------------------------------------------------------------
__device__ __forceinline__ void cvt_one(const float* __restrict__ src,
                                        __half* __restrict__ dst, int i)
{
    float4 f0 = ((const float4*)src)[i*2];
    float4 f1 = ((const float4*)src)[i*2+1];
    uint4 o;
    o.x = h2pack(f0.x, f0.y);
    o.y = h2pack(f0.z, f0.w);
    o.z = h2pack(f1.x, f1.y);
    o.w = h2pack(f1.z, f1.w);
    ((uint4*)dst)[i] = o;
}

__global__ void __launch_bounds__(256) cvt_act(
    const float* __restrict__ Q, const float* __restrict__ K, const float* __restrict__ V)
{
    int i = blockIdx.x * 256 + threadIdx.x;
    if (blockIdx.y == 0)      cvt_one(Q, g_inq, i);
    else if (blockIdx.y == 1) cvt_one(K, g_ink, i);
    else                      cvt_one(V, g_inv, i);
}

__global__ void __launch_bounds__(256) cvt_wt(
    const float* __restrict__ Wq, const float* __restrict__ Wk,
    const float* __restrict__ Wv, const float* __restrict__ Wo)
{
    int i = blockIdx.x * 256 + threadIdx.x;
    if (blockIdx.y == 0)      cvt_one(Wq, g_wq, i);
    else if (blockIdx.y == 1) cvt_one(Wk, g_wk, i);
    else if (blockIdx.y == 2) cvt_one(Wv, g_wv, i);
    else                      cvt_one(Wo, g_wo, i);
}

// ---------------------------------------------------------------------------
// fp16 GEMM (ldmatrix): out[m][n] = sum_k A[m*1024+k]*W[n*1024+k] + bias[n]
// CTA 128x128, K chunks of 64 halves; 8 warps (2m x 4n), warp 64x32.
// 3-stage cp.async ring. smem stage: A 128x72 h + B 128x72 h = 36864 B; x3.
// ---------------------------------------------------------------------------
#define GS_A    18432
#define GS_STG  36864
#define GEMM_SMEM (3*GS_STG)

__device__ __forceinline__ void gemm_h_body(
    const __half* __restrict__ A, const __half* __restrict__ W,
    const float* __restrict__ bias, void* __restrict__ out,
    int mode, float oscale, int bm, int bn, char* smc)
{
    const int tid = threadIdx.x;
    const int wid = tid >> 5, lane = tid & 31;
    const int g = lane >> 2, tig = lane & 3;
    const int wm = (wid & 1) * 64;
    const int wn = (wid >> 1) * 32;
    const uint32_t sbase = smem_u32(smc);

    // ldmatrix per-lane tile-row offsets
    const int aRow = ((lane >> 3) & 1) * 8 + (lane & 7);  // within 16-row m tile
    const int aK   = (lane >> 4) * 8;                     // 0 or 8
    const int bN   = (lane >> 4) * 8 + (lane & 7);        // within 16-col n pair
    const int bK   = ((lane >> 3) & 1) * 8;

    // loaders: row = tid>>1, seg (tid&1)*32 halves
    const int row = tid >> 1, seg = (tid & 1) * 32;
    const __half* gA = A + (size_t)(bm + row) * D_ + seg;
    const __half* gB = W + (size_t)(bn + row) * D_ + seg;
    const uint32_t uA = sbase + (uint32_t)(row*72 + seg) * 2;
    const uint32_t uB = uA + GS_A;

    float c[4][4][4] = {};

    #pragma unroll
    for (int st = 0; st < 2; st++) {
        #pragma unroll
        for (int j = 0; j < 4; j++) {
            CP16(uA + st*GS_STG + j*16, gA + st*64 + j*8);
            CP16(uB + st*GS_STG + j*16, gB + st*64 + j*8);
        }
        CP_COMMIT();
    }

    const int NCH = D_ / 64;   // 16
    for (int it = 0; it < NCH; it++) {
        CP_WAIT1();
        __syncthreads();
        if (it + 2 < NCH) {
            const int ns = (it + 2) % 3;
            #pragma unroll
            for (int j = 0; j < 4; j++) {
                CP16(uA + ns*GS_STG + j*16, gA + (it+2)*64 + j*8);
                CP16(uB + ns*GS_STG + j*16, gB + (it+2)*64 + j*8);
            }
        }
        CP_COMMIT();

        const int cs = it % 3;
        const uint32_t stA = sbase + cs*GS_STG;
        const uint32_t stB = stA + GS_A;
        #pragma unroll
        for (int kt = 0; kt < 4; kt++) {
            uint32_t a[4][4], b[4][2];
            #pragma unroll
            for (int mt = 0; mt < 4; mt++) {
                uint32_t ad = stA + (uint32_t)((wm + mt*16 + aRow)*72 + kt*16 + aK) * 2;
                LDSM4(a[mt][0], a[mt][1], a[mt][2], a[mt][3], ad);
            }
            #pragma unroll
            for (int p = 0; p < 2; p++) {
                uint32_t ad = stB + (uint32_t)((wn + p*16 + bN)*72 + kt*16 + bK) * 2;
                LDSM4(b[2*p][0], b[2*p][1], b[2*p+1][0], b[2*p+1][1], ad);
            }
            #pragma unroll
            for (int mt = 0; mt < 4; mt++)
                #pragma unroll
                for (int nt = 0; nt < 4; nt++)
                    mma16(c[mt][nt], a[mt][0], a[mt][1], a[mt][2], a[mt][3],
                          b[nt][0], b[nt][1]);
        }
    }

    #pragma unroll
    for (int mt = 0; mt < 4; mt++) {
        #pragma unroll
        for (int p = 0; p < 2; p++) {
            int m = bm + wm + mt*16 + g + p*8;
            #pragma unroll
            for (int nt = 0; nt < 4; nt++) {
                int col = bn + wn + nt*8 + tig*2;
                float vx = c[mt][nt][p*2+0] + bias[col];
                float vy = c[mt][nt][p*2+1] + bias[col+1];
                if (mode == 0) {
                    float2 v; v.x = vx; v.y = vy;
                    *(float2*)&((float*)out)[(size_t)m * D_ + col] = v;
                } else if (mode == 1) {
                    int b_ = m >> 11, s = m & 2047;
                    int hh = col >> 6, e = col & 63;
                    __half2 hv = __floats2half2_rn(vx * oscale, vy * oscale);
                    *(__half2*)&((__half*)out)[(((size_t)(b_*H_ + hh)*S_ + s))*HD_ + e] = hv;
                } else {
                    int b_ = m >> 11, s = m & 2047;
                    int hh = col >> 6, e = col & 63;
                    __half* dst = (__half*)out + ((size_t)(b_*H_ + hh)*HD_)*S_;
                    dst[(size_t)(e  )*S_ + s] = __float2half_rn(vx);
                    dst[(size_t)(e+1)*S_ + s] = __float2half_rn(vy);
                }
            }
        }
    }
}

__global__ void __launch_bounds__(256, 2) proj_qkv(
    const float* __restrict__ bq, const float* __restrict__ bk, const float* __restrict__ bv)
{
    extern __shared__ char smc[];
    const __half *A, *W; const float* bias; void* out; float sc; int mode;
    if (blockIdx.z == 0)      { A = g_inq; W = g_wq; bias = bq; out = g_qh; sc = 0.125f; mode = 1; }
    else if (blockIdx.z == 1) { A = g_ink; W = g_wk; bias = bk; out = g_kh; sc = 1.0f;   mode = 1; }
    else                      { A = g_inv; W = g_wv; bias = bv; out = g_vt; sc = 1.0f;   mode = 2; }
    gemm_h_body(A, W, bias, out, mode, sc, blockIdx.y*128, blockIdx.x*128, smc);
}

__global__ void __launch_bounds__(256, 2) out_proj(
    const float* __restrict__ bias, float* __restrict__ out)
{
    extern __shared__ char smc[];
    gemm_h_body(g_atth, g_wo, bias, out, 0, 1.0f, blockIdx.y*128, blockIdx.x*128, smc);
}

// ---------------------------------------------------------------------------
// fp16 flash attention (ldmatrix): 256 thr / 8 warps, 16 q-rows per warp,
// K/V 64-row blocks, 3-stage cp.async ring. V transposed => PV B-frags direct.
// smem: Qs 128x72 h (18432) + 3 stages of (K 64x72 + V 64x72) (18432 each).
// ---------------------------------------------------------------------------
#define KV_STG   18432
#define ATTN_SMEM (18432 + 3*KV_STG)   // 73728
#define NITER (S_/64)

__global__ void __launch_bounds__(256, 2) attn_h()
{
    extern __shared__ char smc[];
    const int bh = blockIdx.y;
    const int b  = bh >> 4, h = bh & 15;
    const int q0 = blockIdx.x * 128;
    const __half* qp  = g_qh + (size_t)bh * S_ * HD_;
    const __half* kp  = g_kh + (size_t)bh * S_ * HD_;
    const __half* vtp = g_vt + (size_t)bh * HD_ * S_;

    const int tid = threadIdx.x;
    const int wid = tid >> 5, lane = tid & 31;
    const int g = lane >> 2, tig = lane & 3;
    const int wrow = wid * 16;
    const uint32_t sbase = smem_u32(smc);

    const int aRow = ((lane >> 3) & 1) * 8 + (lane & 7);
    const int aK   = (lane >> 4) * 8;
    const int bN   = (lane >> 4) * 8 + (lane & 7);
    const int bK   = ((lane >> 3) & 1) * 8;

    // Q: 128 rows x 64 halves
    {
        int row = tid >> 1, seg = (tid & 1) * 32;
        uint32_t dst = sbase + (uint32_t)(row*72 + seg) * 2;
        const __half* src = qp + (size_t)(q0 + row) * HD_ + seg;
        #pragma unroll
        for (int j = 0; j < 4; j++) CP16(dst + j*16, src + j*8);
    }
    const int kvr = tid >> 2, kvs = (tid & 3) * 16;
    const uint32_t ukb = sbase + 18432 + (uint32_t)(kvr*72 + kvs) * 2;
    const uint32_t uvb = ukb + 9216;
    #pragma unroll
    for (int st = 0; st < 2; st++) {
        const __half* sk = kp  + (size_t)(st*64 + kvr) * HD_ + kvs;
        const __half* sv = vtp + (size_t)kvr * S_ + st*64 + kvs;
        CP16(ukb + st*KV_STG,      sk);
        CP16(ukb + st*KV_STG + 16, sk + 8);
        CP16(uvb + st*KV_STG,      sv);
        CP16(uvb + st*KV_STG + 16, sv + 8);
        CP_COMMIT();
    }

    float mx0 = -1e30f, mx1 = -1e30f, l0 = 0.f, l1 = 0.f;
    float acc[8][4] = {};

    for (int it = 0; it < NITER; it++) {
        CP_WAIT1();
        __syncthreads();
        if (it + 2 < NITER) {
            const int ns = (it + 2) % 3;
            const __half* sk = kp  + (size_t)((it+2)*64 + kvr) * HD_ + kvs;
            const __half* sv = vtp + (size_t)kvr * S_ + (it+2)*64 + kvs;
            CP16(ukb + ns*KV_STG,      sk);
            CP16(ukb + ns*KV_STG + 16, sk + 8);
            CP16(uvb + ns*KV_STG,      sv);
            CP16(uvb + ns*KV_STG + 16, sv + 8);
        }
        CP_COMMIT();

        const int cs = it % 3;
        const uint32_t stK = sbase + 18432 + cs*KV_STG;
        const uint32_t stV = stK + 9216;
        const uint32_t stQ = sbase;

        // S = Q K^T : warp tile 16 x 64, 4 k16 steps
        float s[8][4] = {};
        #pragma unroll
        for (int kt = 0; kt < 4; kt++) {
            uint32_t a0, a1, a2, a3;
            LDSM4(a0, a1, a2, a3,
                  stQ + (uint32_t)((wrow + aRow)*72 + kt*16 + aK) * 2);
            uint32_t bb[8][2];
            #pragma unroll
            for (int p = 0; p < 4; p++) {
                uint32_t ad = stK + (uint32_t)((p*16 + bN)*72 + kt*16 + bK) * 2;
                LDSM4(bb[2*p][0], bb[2*p][1], bb[2*p+1][0], bb[2*p+1][1], ad);
            }
            #pragma unroll
            for (int nt = 0; nt < 8; nt++)
                mma16(s[nt], a0, a1, a2, a3, bb[nt][0], bb[nt][1]);
        }

        // online softmax
        float rm0 = -1e30f, rm1 = -1e30f;
        #pragma unroll
        for (int nt = 0; nt < 8; nt++) {
            rm0 = fmaxf(rm0, fmaxf(s[nt][0], s[nt][1]));
            rm1 = fmaxf(rm1, fmaxf(s[nt][2], s[nt][3]));
        }
        rm0 = fmaxf(rm0, __shfl_xor_sync(0xffffffffu, rm0, 1));
        rm0 = fmaxf(rm0, __shfl_xor_sync(0xffffffffu, rm0, 2));
        rm1 = fmaxf(rm1, __shfl_xor_sync(0xffffffffu, rm1, 1));
        rm1 = fmaxf(rm1, __shfl_xor_sync(0xffffffffu, rm1, 2));

        float nm0 = fmaxf(mx0, rm0), nm1 = fmaxf(mx1, rm1);
        float al0 = __expf(mx0 - nm0), al1 = __expf(mx1 - nm1);
        mx0 = nm0; mx1 = nm1;

        float sum0 = 0.f, sum1 = 0.f;
        #pragma unroll
        for (int nt = 0; nt < 8; nt++) {
            float p0 = __expf(s[nt][0] - nm0);
            float p1 = __expf(s[nt][1] - nm0);
            float p2 = __expf(s[nt][2] - nm1);
            float p3 = __expf(s[nt][3] - nm1);
            sum0 += p0 + p1; sum1 += p2 + p3;
            s[nt][0] = p0; s[nt][1] = p1; s[nt][2] = p2; s[nt][3] = p3;
        }
        sum0 += __shfl_xor_sync(0xffffffffu, sum0, 1);
        sum0 += __shfl_xor_sync(0xffffffffu, sum0, 2);
        sum1 += __shfl_xor_sync(0xffffffffu, sum1, 1);
        sum1 += __shfl_xor_sync(0xffffffffu, sum1, 2);
        l0 = l0 * al0 + sum0;
        l1 = l1 * al1 + sum1;

        #pragma unroll
        for (int nt = 0; nt < 8; nt++) {
            acc[nt][0] *= al0; acc[nt][1] *= al0;
            acc[nt][2] *= al1; acc[nt][3] *= al1;
        }

        // acc += P * V
        #pragma unroll
        for (int kt = 0; kt < 4; kt++) {
            uint32_t pa0 = h2pack(s[2*kt  ][0], s[2*kt  ][1]);
            uint32_t pa1 = h2pack(s[2*kt  ][2], s[2*kt  ][3]);
            uint32_t pa2 = h2pack(s[2*kt+1][0], s[2*kt+1][1]);
            uint32_t pa3 = h2pack(s[2*kt+1][2], s[2*kt+1][3]);
            uint32_t bb[8][2];
            #pragma unroll
            for (int p = 0; p < 4; p++) {
                uint32_t ad = stV + (uint32_t)((p*16 + bN)*72 + kt*16 + bK) * 2;
                LDSM4(bb[2*p][0], bb[2*p][1], bb[2*p+1][0], bb[2*p+1][1], ad);
            }
            #pragma unroll
            for (int nt = 0; nt < 8; nt++)
                mma16(acc[nt], pa0, pa1, pa2, pa3, bb[nt][0], bb[nt][1]);
        }
    }

    // epilogue
    float inv0 = 1.0f / l0, inv1 = 1.0f / l1;
    int r0 = q0 + wrow + g;
    int r1 = r0 + 8;
    #pragma unroll
    for (int nt = 0; nt < 8; nt++) {
        int col = h*64 + nt*8 + tig*2;
        *(__half2*)&g_atth[(size_t)(b*S_ + r0)*D_ + col] =
            __floats2half2_rn(acc[nt][0]*inv0, acc[nt][1]*inv0);
        *(__half2*)&g_atth[(size_t)(b*S_ + r1)*D_ + col] =
            __floats2half2_rn(acc[nt][2]*inv1, acc[nt][3]*inv1);
    }
}

// ---------------------------------------------------------------------------
extern "C" void kernel_launch(void* const* d_in, const int* in_sizes, int n_in,
                              void* d_out, int out_size)
{
    const float* V  = (const float*)d_in[0];
    const float* K  = (const float*)d_in[1];
    const float* Q  = (const float*)d_in[2];
    const float* Wv = (const float*)d_in[3];
    const float* bv = (const float*)d_in[4];
    const float* Wk = (const float*)d_in[5];
    const float* bk = (const float*)d_in[6];
    const float* Wq = (const float*)d_in[7];
    const float* bq = (const float*)d_in[8];
    const float* Wo = (const float*)d_in[9];
    const float* bo = (const float*)d_in[10];
    float* out = (float*)d_out;

    (void)in_sizes; (void)n_in; (void)out_size;

    dim3 gact(MROWS*D_/8/256, 3);    // (2048, 3)
    cvt_act<<<gact, 256>>>(Q, K, V);
    dim3 gwt(D_*D_/8/256, 4);        // (512, 4)
    cvt_wt<<<gwt, 256>>>(Wq, Wk, Wv, Wo);

    cudaFuncSetAttribute(proj_qkv, cudaFuncAttributeMaxDynamicSharedMemorySize, GEMM_SMEM);
    cudaFuncSetAttribute(out_proj, cudaFuncAttributeMaxDynamicSharedMemorySize, GEMM_SMEM);
    cudaFuncSetAttribute(attn_h,   cudaFuncAttributeMaxDynamicSharedMemorySize, ATTN_SMEM);

    dim3 gproj(D_/128, MROWS/128, 3);   // (8, 32, 3)
    proj_qkv<<<gproj, 256, GEMM_SMEM>>>(bq, bk, bv);

    dim3 ga_grid(S_/128, B_*H_);        // (16, 32)
    attn_h<<<ga_grid, 256, ATTN_SMEM>>>();

    dim3 gout(D_/128, MROWS/128);       // (8, 32)
    out_proj<<<gout, 256, GEMM_SMEM>>>(bo, out);
}

// round 11
// speedup vs baseline: 4.3125x; 1.0504x over previous
#include <cuda_runtime.h>
#include <cuda_fp16.h>
#include <math.h>
#include <stdint.h>

#define H_  16
#define HD_ 64
#define D_  1024
#define B_  2
#define S_  2048
#define MROWS (B_*S_)   // 4096

// fp16 scratch
__device__ __half g_inq[(size_t)MROWS*D_];
__device__ __half g_ink[(size_t)MROWS*D_];
__device__ __half g_inv[(size_t)MROWS*D_];
__device__ __half g_wq[(size_t)D_*D_];
__device__ __half g_wk[(size_t)D_*D_];
__device__ __half g_wv[(size_t)D_*D_];
__device__ __half g_wo[(size_t)D_*D_];
__device__ __half g_qh[(size_t)B_*H_*S_*HD_];  // q proj, pre-scaled 0.125*log2(e)
__device__ __half g_kh[(size_t)B_*H_*S_*HD_];
__device__ __half g_vt[(size_t)B_*H_*HD_*S_];  // v proj, transposed [B,H,HD,S]
__device__ __half g_atth[(size_t)MROWS*D_];    // attention out, concat, half

// ---------------------------------------------------------------------------
__device__ __forceinline__ void mma16(float* c,
    uint32_t a0, uint32_t a1, uint32_t a2, uint32_t a3,
    uint32_t b0, uint32_t b1)
{
    asm volatile(
        "mma.sync.aligned.m16n8k16.row.col.f32.f16.f16.f32 "
        "{%0,%1,%2,%3}, {%4,%5,%6,%7}, {%8,%9}, {%0,%1,%2,%3};"
        : "+f"(c[0]), "+f"(c[1]), "+f"(c[2]), "+f"(c[3])
        : "r"(a0), "r"(a1), "r"(a2), "r"(a3), "r"(b0), "r"(b1));
}

#define LDSM4(r0, r1, r2, r3, addr) \
    asm volatile("ldmatrix.sync.aligned.m8n8.x4.shared.b16 {%0,%1,%2,%3}, [%4];" \
        : "=r"(r0), "=r"(r1), "=r"(r2), "=r"(r3) : "r"(addr))

__device__ __forceinline__ uint32_t smem_u32(const void* p) {
    uint32_t a;
    asm("{ .reg .u64 t; cvta.to.shared.u64 t, %1; cvt.u32.u64 %0, t; }"
        : "=r"(a) : "l"(p));
    return a;
}
__device__ __forceinline__ uint32_t h2pack(float x, float y) {
    __half2 h = __floats2half2_rn(x, y);
    return *(uint32_t*)&h;
}
// exp2 on a packed half2 (one MUFU op per pair)
__device__ __forceinline__ uint32_t ex2_h2(uint32_t x) {
    uint32_t r;
    asm("ex2.approx.f16x2 %0, %1;" : "=r"(r) : "r"(x));
    return r;
}

#define CP16(dst, src) \
    asm volatile("cp.async.cg.shared.global [%0], [%1], 16;" \
        :: "r"(dst), "l"(src) : "memory")
#define CP_COMMIT() asm volatile("cp.async.commit_group;" ::: "memory")
#define CP_WAIT1()  asm volatile("cp.async.wait_group 1;" ::: "memory")

#define ONES_H2 0x3C003C00u   // half2(1.0, 1.0)

// ---------------------------------------------------------------------------
// fp32 -> fp16 converts, fused via blockIdx.y
// ---------------------------------------------------------------------------
__device__ __forceinline__ void cvt_one(const float* __restrict__ src,
                                        __half* __restrict__ dst, int i)
{
    float4 f0 = ((const float4*)src)[i*2];
    float4 f1 = ((const float4*)src)[i*2+1];
    uint4 o;
    o.x = h2pack(f0.x, f0.y);
    o.y = h2pack(f0.z, f0.w);
    o.z = h2pack(f1.x, f1.y);
    o.w = h2pack(f1.z, f1.w);
    ((uint4*)dst)[i] = o;
}

__global__ void __launch_bounds__(256) cvt_act(
    const float* __restrict__ Q, const float* __restrict__ K, const float* __restrict__ V)
{
    int i = blockIdx.x * 256 + threadIdx.x;
    if (blockIdx.y == 0)      cvt_one(Q, g_inq, i);
    else if (blockIdx.y == 1) cvt_one(K, g_ink, i);
    else                      cvt_one(V, g_inv, i);
}

__global__ void __launch_bounds__(256) cvt_wt(
    const float* __restrict__ Wq, const float* __restrict__ Wk,
    const float* __restrict__ Wv, const float* __restrict__ Wo)
{
    int i = blockIdx.x * 256 + threadIdx.x;
    if (blockIdx.y == 0)      cvt_one(Wq, g_wq, i);
    else if (blockIdx.y == 1) cvt_one(Wk, g_wk, i);
    else if (blockIdx.y == 2) cvt_one(Wv, g_wv, i);
    else                      cvt_one(Wo, g_wo, i);
}

// ---------------------------------------------------------------------------
// fp16 GEMM (ldmatrix) — unchanged from R10.
// ---------------------------------------------------------------------------
#define GS_A    18432
#define GS_STG  36864
#define GEMM_SMEM (3*GS_STG)

__device__ __forceinline__ void gemm_h_body(
    const __half* __restrict__ A, const __half* __restrict__ W,
    const float* __restrict__ bias, void* __restrict__ out,
    int mode, float oscale, int bm, int bn, char* smc)
{
    const int tid = threadIdx.x;
    const int wid = tid >> 5, lane = tid & 31;
    const int g = lane >> 2, tig = lane & 3;
    const int wm = (wid & 1) * 64;
    const int wn = (wid >> 1) * 32;
    const uint32_t sbase = smem_u32(smc);

    const int aRow = ((lane >> 3) & 1) * 8 + (lane & 7);
    const int aK   = (lane >> 4) * 8;
    const int bN   = (lane >> 4) * 8 + (lane & 7);
    const int bK   = ((lane >> 3) & 1) * 8;

    const int row = tid >> 1, seg = (tid & 1) * 32;
    const __half* gA = A + (size_t)(bm + row) * D_ + seg;
    const __half* gB = W + (size_t)(bn + row) * D_ + seg;
    const uint32_t uA = sbase + (uint32_t)(row*72 + seg) * 2;
    const uint32_t uB = uA + GS_A;

    float c[4][4][4] = {};

    #pragma unroll
    for (int st = 0; st < 2; st++) {
        #pragma unroll
        for (int j = 0; j < 4; j++) {
            CP16(uA + st*GS_STG + j*16, gA + st*64 + j*8);
            CP16(uB + st*GS_STG + j*16, gB + st*64 + j*8);
        }
        CP_COMMIT();
    }

    const int NCH = D_ / 64;
    for (int it = 0; it < NCH; it++) {
        CP_WAIT1();
        __syncthreads();
        if (it + 2 < NCH) {
            const int ns = (it + 2) % 3;
            #pragma unroll
            for (int j = 0; j < 4; j++) {
                CP16(uA + ns*GS_STG + j*16, gA + (it+2)*64 + j*8);
                CP16(uB + ns*GS_STG + j*16, gB + (it+2)*64 + j*8);
            }
        }
        CP_COMMIT();

        const int cs = it % 3;
        const uint32_t stA = sbase + cs*GS_STG;
        const uint32_t stB = stA + GS_A;
        #pragma unroll
        for (int kt = 0; kt < 4; kt++) {
            uint32_t a[4][4], b[4][2];
            #pragma unroll
            for (int mt = 0; mt < 4; mt++) {
                uint32_t ad = stA + (uint32_t)((wm + mt*16 + aRow)*72 + kt*16 + aK) * 2;
                LDSM4(a[mt][0], a[mt][1], a[mt][2], a[mt][3], ad);
            }
            #pragma unroll
            for (int p = 0; p < 2; p++) {
                uint32_t ad = stB + (uint32_t)((wn + p*16 + bN)*72 + kt*16 + bK) * 2;
                LDSM4(b[2*p][0], b[2*p][1], b[2*p+1][0], b[2*p+1][1], ad);
            }
            #pragma unroll
            for (int mt = 0; mt < 4; mt++)
                #pragma unroll
                for (int nt = 0; nt < 4; nt++)
                    mma16(c[mt][nt], a[mt][0], a[mt][1], a[mt][2], a[mt][3],
                          b[nt][0], b[nt][1]);
        }
    }

    #pragma unroll
    for (int mt = 0; mt < 4; mt++) {
        #pragma unroll
        for (int p = 0; p < 2; p++) {
            int m = bm + wm + mt*16 + g + p*8;
            #pragma unroll
            for (int nt = 0; nt < 4; nt++) {
                int col = bn + wn + nt*8 + tig*2;
                float vx = c[mt][nt][p*2+0] + bias[col];
                float vy = c[mt][nt][p*2+1] + bias[col+1];
                if (mode == 0) {
                    float2 v; v.x = vx; v.y = vy;
                    *(float2*)&((float*)out)[(size_t)m * D_ + col] = v;
                } else if (mode == 1) {
                    int b_ = m >> 11, s = m & 2047;
                    int hh = col >> 6, e = col & 63;
                    __half2 hv = __floats2half2_rn(vx * oscale, vy * oscale);
                    *(__half2*)&((__half*)out)[(((size_t)(b_*H_ + hh)*S_ + s))*HD_ + e] = hv;
                } else {
                    int b_ = m >> 11, s = m & 2047;
                    int hh = col >> 6, e = col & 63;
                    __half* dst = (__half*)out + ((size_t)(b_*H_ + hh)*HD_)*S_;
                    dst[(size_t)(e  )*S_ + s] = __float2half_rn(vx);
                    dst[(size_t)(e+1)*S_ + s] = __float2half_rn(vy);
                }
            }
        }
    }
}

__global__ void __launch_bounds__(256, 2) proj_qkv(
    const float* __restrict__ bq, const float* __restrict__ bk, const float* __restrict__ bv)
{
    extern __shared__ char smc[];
    const __half *A, *W; const float* bias; void* out; float sc; int mode;
    // Q pre-scale folds softmax scale AND log2(e): scores land in log2 domain.
    if (blockIdx.z == 0)      { A = g_inq; W = g_wq; bias = bq; out = g_qh;
                                sc = 0.125f * 1.4426950408889634f; mode = 1; }
    else if (blockIdx.z == 1) { A = g_ink; W = g_wk; bias = bk; out = g_kh; sc = 1.0f; mode = 1; }
    else                      { A = g_inv; W = g_wv; bias = bv; out = g_vt; sc = 1.0f; mode = 2; }
    gemm_h_body(A, W, bias, out, mode, sc, blockIdx.y*128, blockIdx.x*128, smc);
}

__global__ void __launch_bounds__(256, 2) out_proj(
    const float* __restrict__ bias, float* __restrict__ out)
{
    extern __shared__ char smc[];
    gemm_h_body(g_atth, g_wo, bias, out, 0, 1.0f, blockIdx.y*128, blockIdx.x*128, smc);
}

// ---------------------------------------------------------------------------
// fp16 flash attention, log2-domain softmax + f16x2 exp + ones-mma row sums.
// 256 thr / 8 warps, 16 q-rows per warp, K/V 64 blocks, 3-stage cp.async.
// ---------------------------------------------------------------------------
#define KV_STG   18432
#define ATTN_SMEM (18432 + 3*KV_STG)   // 73728
#define NITER (S_/64)

__global__ void __launch_bounds__(256, 2) attn_h()
{
    extern __shared__ char smc[];
    const int bh = blockIdx.y;
    const int b  = bh >> 4, h = bh & 15;
    const int q0 = blockIdx.x * 128;
    const __half* qp  = g_qh + (size_t)bh * S_ * HD_;
    const __half* kp  = g_kh + (size_t)bh * S_ * HD_;
    const __half* vtp = g_vt + (size_t)bh * HD_ * S_;

    const int tid = threadIdx.x;
    const int wid = tid >> 5, lane = tid & 31;
    const int g = lane >> 2, tig = lane & 3;
    const int wrow = wid * 16;
    const uint32_t sbase = smem_u32(smc);

    const int aRow = ((lane >> 3) & 1) * 8 + (lane & 7);
    const int aK   = (lane >> 4) * 8;
    const int bN   = (lane >> 4) * 8 + (lane & 7);
    const int bK   = ((lane >> 3) & 1) * 8;

    {
        int row = tid >> 1, seg = (tid & 1) * 32;
        uint32_t dst = sbase + (uint32_t)(row*72 + seg) * 2;
        const __half* src = qp + (size_t)(q0 + row) * HD_ + seg;
        #pragma unroll
        for (int j = 0; j < 4; j++) CP16(dst + j*16, src + j*8);
    }
    const int kvr = tid >> 2, kvs = (tid & 3) * 16;
    const uint32_t ukb = sbase + 18432 + (uint32_t)(kvr*72 + kvs) * 2;
    const uint32_t uvb = ukb + 9216;
    #pragma unroll
    for (int st = 0; st < 2; st++) {
        const __half* sk = kp  + (size_t)(st*64 + kvr) * HD_ + kvs;
        const __half* sv = vtp + (size_t)kvr * S_ + st*64 + kvs;
        CP16(ukb + st*KV_STG,      sk);
        CP16(ukb + st*KV_STG + 16, sk + 8);
        CP16(uvb + st*KV_STG,      sv);
        CP16(uvb + st*KV_STG + 16, sv + 8);
        CP_COMMIT();
    }

    float mx0 = -1e30f, mx1 = -1e30f;
    float acc[8][4] = {};
    float lacc[4] = {};   // row sums via ones-mma (cols identical; use [0],[2])

    for (int it = 0; it < NITER; it++) {
        CP_WAIT1();
        __syncthreads();
        if (it + 2 < NITER) {
            const int ns = (it + 2) % 3;
            const __half* sk = kp  + (size_t)((it+2)*64 + kvr) * HD_ + kvs;
            const __half* sv = vtp + (size_t)kvr * S_ + (it+2)*64 + kvs;
            CP16(ukb + ns*KV_STG,      sk);
            CP16(ukb + ns*KV_STG + 16, sk + 8);
            CP16(uvb + ns*KV_STG,      sv);
            CP16(uvb + ns*KV_STG + 16, sv + 8);
        }
        CP_COMMIT();

        const int cs = it % 3;
        const uint32_t stK = sbase + 18432 + cs*KV_STG;
        const uint32_t stV = stK + 9216;
        const uint32_t stQ = sbase;

        // S (log2 domain) = Q K^T : warp tile 16 x 64
        float s[8][4] = {};
        #pragma unroll
        for (int kt = 0; kt < 4; kt++) {
            uint32_t a0, a1, a2, a3;
            LDSM4(a0, a1, a2, a3,
                  stQ + (uint32_t)((wrow + aRow)*72 + kt*16 + aK) * 2);
            uint32_t bb[8][2];
            #pragma unroll
            for (int p = 0; p < 4; p++) {
                uint32_t ad = stK + (uint32_t)((p*16 + bN)*72 + kt*16 + bK) * 2;
                LDSM4(bb[2*p][0], bb[2*p][1], bb[2*p+1][0], bb[2*p+1][1], ad);
            }
            #pragma unroll
            for (int nt = 0; nt < 8; nt++)
                mma16(s[nt], a0, a1, a2, a3, bb[nt][0], bb[nt][1]);
        }

        // online max (rows wrow+g, wrow+g+8)
        float rm0 = -1e30f, rm1 = -1e30f;
        #pragma unroll
        for (int nt = 0; nt < 8; nt++) {
            rm0 = fmaxf(rm0, fmaxf(s[nt][0], s[nt][1]));
            rm1 = fmaxf(rm1, fmaxf(s[nt][2], s[nt][3]));
        }
        rm0 = fmaxf(rm0, __shfl_xor_sync(0xffffffffu, rm0, 1));
        rm0 = fmaxf(rm0, __shfl_xor_sync(0xffffffffu, rm0, 2));
        rm1 = fmaxf(rm1, __shfl_xor_sync(0xffffffffu, rm1, 1));
        rm1 = fmaxf(rm1, __shfl_xor_sync(0xffffffffu, rm1, 2));

        float nm0 = fmaxf(mx0, rm0), nm1 = fmaxf(mx1, rm1);
        float al0 = exp2f(mx0 - nm0), al1 = exp2f(mx1 - nm1);
        mx0 = nm0; mx1 = nm1;

        // P = exp2(s - nm), computed pairwise in half2 (A-frag layout)
        uint32_t ph[8][2];
        #pragma unroll
        for (int nt = 0; nt < 8; nt++) {
            ph[nt][0] = ex2_h2(h2pack(s[nt][0] - nm0, s[nt][1] - nm0));
            ph[nt][1] = ex2_h2(h2pack(s[nt][2] - nm1, s[nt][3] - nm1));
        }

        // rescale accumulators (incl. row-sum acc)
        #pragma unroll
        for (int nt = 0; nt < 8; nt++) {
            acc[nt][0] *= al0; acc[nt][1] *= al0;
            acc[nt][2] *= al1; acc[nt][3] *= al1;
        }
        lacc[0] *= al0; lacc[1] *= al0; lacc[2] *= al1; lacc[3] *= al1;

        // acc += P * V ; lacc += P * ones
        #pragma unroll
        for (int kt = 0; kt < 4; kt++) {
            uint32_t pa0 = ph[2*kt  ][0];
            uint32_t pa1 = ph[2*kt  ][1];
            uint32_t pa2 = ph[2*kt+1][0];
            uint32_t pa3 = ph[2*kt+1][1];
            uint32_t bb[8][2];
            #pragma unroll
            for (int p = 0; p < 4; p++) {
                uint32_t ad = stV + (uint32_t)((p*16 + bN)*72 + kt*16 + bK) * 2;
                LDSM4(bb[2*p][0], bb[2*p][1], bb[2*p+1][0], bb[2*p+1][1], ad);
            }
            #pragma unroll
            for (int nt = 0; nt < 8; nt++)
                mma16(acc[nt], pa0, pa1, pa2, pa3, bb[nt][0], bb[nt][1]);
            mma16(lacc, pa0, pa1, pa2, pa3, ONES_H2, ONES_H2);
        }
    }

    // epilogue: normalize, store half concat layout
    float inv0 = 1.0f / lacc[0], inv1 = 1.0f / lacc[2];
    int r0 = q0 + wrow + g;
    int r1 = r0 + 8;
    #pragma unroll
    for (int nt = 0; nt < 8; nt++) {
        int col = h*64 + nt*8 + tig*2;
        *(__half2*)&g_atth[(size_t)(b*S_ + r0)*D_ + col] =
            __floats2half2_rn(acc[nt][0]*inv0, acc[nt][1]*inv0);
        *(__half2*)&g_atth[(size_t)(b*S_ + r1)*D_ + col] =
            __floats2half2_rn(acc[nt][2]*inv1, acc[nt][3]*inv1);
    }
}

// ---------------------------------------------------------------------------
extern "C" void kernel_launch(void* const* d_in, const int* in_sizes, int n_in,
                              void* d_out, int out_size)
{
    const float* V  = (const float*)d_in[0];
    const float* K  = (const float*)d_in[1];
    const float* Q  = (const float*)d_in[2];
    const float* Wv = (const float*)d_in[3];
    const float* bv = (const float*)d_in[4];
    const float* Wk = (const float*)d_in[5];
    const float* bk = (const float*)d_in[6];
    const float* Wq = (const float*)d_in[7];
    const float* bq = (const float*)d_in[8];
    const float* Wo = (const float*)d_in[9];
    const float* bo = (const float*)d_in[10];
    float* out = (float*)d_out;

    (void)in_sizes; (void)n_in; (void)out_size;

    dim3 gact(MROWS*D_/8/256, 3);
    cvt_act<<<gact, 256>>>(Q, K, V);
    dim3 gwt(D_*D_/8/256, 4);
    cvt_wt<<<gwt, 256>>>(Wq, Wk, Wv, Wo);

    cudaFuncSetAttribute(proj_qkv, cudaFuncAttributeMaxDynamicSharedMemorySize, GEMM_SMEM);
    cudaFuncSetAttribute(out_proj, cudaFuncAttributeMaxDynamicSharedMemorySize, GEMM_SMEM);
    cudaFuncSetAttribute(attn_h,   cudaFuncAttributeMaxDynamicSharedMemorySize, ATTN_SMEM);

    dim3 gproj(D_/128, MROWS/128, 3);
    proj_qkv<<<gproj, 256, GEMM_SMEM>>>(bq, bk, bv);

    dim3 ga_grid(S_/128, B_*H_);
    attn_h<<<ga_grid, 256, ATTN_SMEM>>>();

    dim3 gout(D_/128, MROWS/128);
    out_proj<<<gout, 256, GEMM_SMEM>>>(bo, out);
}

// round 13
// speedup vs baseline: 4.4963x; 1.0426x over previous
#include <cuda_runtime.h>
#include <cuda_fp16.h>
#include <math.h>
#include <stdint.h>

#define H_  16
#define HD_ 64
#define D_  1024
#define B_  2
#define S_  2048
#define MROWS (B_*S_)   // 4096

// fp16 scratch
__device__ __half g_inq[(size_t)MROWS*D_];
__device__ __half g_ink[(size_t)MROWS*D_];
__device__ __half g_inv[(size_t)MROWS*D_];
__device__ __half g_wq[(size_t)D_*D_];
__device__ __half g_wk[(size_t)D_*D_];
__device__ __half g_wv[(size_t)D_*D_];
__device__ __half g_wo[(size_t)D_*D_];
__device__ __half g_qh[(size_t)B_*H_*S_*HD_];  // q proj, pre-scaled 0.125*log2(e)
__device__ __half g_kh[(size_t)B_*H_*S_*HD_];
__device__ __half g_vt[(size_t)B_*H_*HD_*S_];  // v proj, transposed [B,H,HD,S]
__device__ __half g_atth[(size_t)MROWS*D_];    // attention out, concat, half

// ---------------------------------------------------------------------------
__device__ __forceinline__ void mma16(float* c,
    uint32_t a0, uint32_t a1, uint32_t a2, uint32_t a3,
    uint32_t b0, uint32_t b1)
{
    asm volatile(
        "mma.sync.aligned.m16n8k16.row.col.f32.f16.f16.f32 "
        "{%0,%1,%2,%3}, {%4,%5,%6,%7}, {%8,%9}, {%0,%1,%2,%3};"
        : "+f"(c[0]), "+f"(c[1]), "+f"(c[2]), "+f"(c[3])
        : "r"(a0), "r"(a1), "r"(a2), "r"(a3), "r"(b0), "r"(b1));
}

#define LDSM4(r0, r1, r2, r3, addr) \
    asm volatile("ldmatrix.sync.aligned.m8n8.x4.shared.b16 {%0,%1,%2,%3}, [%4];" \
        : "=r"(r0), "=r"(r1), "=r"(r2), "=r"(r3) : "r"(addr))

__device__ __forceinline__ uint32_t smem_u32(const void* p) {
    uint32_t a;
    asm("{ .reg .u64 t; cvta.to.shared.u64 t, %1; cvt.u32.u64 %0, t; }"
        : "=r"(a) : "l"(p));
    return a;
}
__device__ __forceinline__ uint32_t h2pack(float x, float y) {
    __half2 h = __floats2half2_rn(x, y);
    return *(uint32_t*)&h;
}
__device__ __forceinline__ uint32_t ex2_h2(uint32_t x) {
    uint32_t r;
    asm("ex2.approx.f16x2 %0, %1;" : "=r"(r) : "r"(x));
    return r;
}

#define CP16(dst, src) \
    asm volatile("cp.async.cg.shared.global [%0], [%1], 16;" \
        :: "r"(dst), "l"(src) : "memory")
#define CP_COMMIT() asm volatile("cp.async.commit_group;" ::: "memory")
#define CP_WAIT0()  asm volatile("cp.async.wait_group 0;" ::: "memory")
#define CP_WAIT2()  asm volatile("cp.async.wait_group 2;" ::: "memory")

#define ONES_H2 0x3C003C00u   // half2(1.0, 1.0)

// ---------------------------------------------------------------------------
// fp32 -> fp16 converts, fused via blockIdx.y
// ---------------------------------------------------------------------------
__device__ __forceinline__ void cvt_one(const float* __restrict__ src,
                                        __half* __restrict__ dst, int i)
{
    float4 f0 = ((const float4*)src)[i*2];
    float4 f1 = ((const float4*)src)[i*2+1];
    uint4 o;
    o.x = h2pack(f0.x, f0.y);
    o.y = h2pack(f0.z, f0.w);
    o.z = h2pack(f1.x, f1.y);
    o.w = h2pack(f1.z, f1.w);
    ((uint4*)dst)[i] = o;
}

__global__ void __launch_bounds__(256) cvt_act(
    const float* __restrict__ Q, const float* __restrict__ K, const float* __restrict__ V)
{
    int i = blockIdx.x * 256 + threadIdx.x;
    if (blockIdx.y == 0)      cvt_one(Q, g_inq, i);
    else if (blockIdx.y == 1) cvt_one(K, g_ink, i);
    else                      cvt_one(V, g_inv, i);
}

__global__ void __launch_bounds__(256) cvt_wt(
    const float* __restrict__ Wq, const float* __restrict__ Wk,
    const float* __restrict__ Wv, const float* __restrict__ Wo)
{
    int i = blockIdx.x * 256 + threadIdx.x;
    if (blockIdx.y == 0)      cvt_one(Wq, g_wq, i);
    else if (blockIdx.y == 1) cvt_one(Wk, g_wk, i);
    else if (blockIdx.y == 2) cvt_one(Wv, g_wv, i);
    else                      cvt_one(Wo, g_wo, i);
}

// ---------------------------------------------------------------------------
// fp16 GEMM (ldmatrix): 2-stage ring, loop unrolled x2 => compile-time stage
// CTA 128x128, K chunks of 64 halves; 8 warps (2m x 4n), warp 64x32.
// smem stage: A 128x72 h + B 128x72 h = 36864 B; x2 = 73728.
// ---------------------------------------------------------------------------
#define GS_A    18432
#define GS_STG  36864
#define GEMM_SMEM (2*GS_STG)   // 73728

__device__ __forceinline__ void gemm_h_body(
    const __half* __restrict__ A, const __half* __restrict__ W,
    const float* __restrict__ bias, void* __restrict__ out,
    int mode, float oscale, int bm, int bn, char* smc)
{
    const int tid = threadIdx.x;
    const int wid = tid >> 5, lane = tid & 31;
    const int g = lane >> 2, tig = lane & 3;
    const int wm = (wid & 1) * 64;
    const int wn = (wid >> 1) * 32;
    const uint32_t sbase = smem_u32(smc);

    const int aRow = ((lane >> 3) & 1) * 8 + (lane & 7);
    const int aK   = (lane >> 4) * 8;
    const int bN   = (lane >> 4) * 8 + (lane & 7);
    const int bK   = ((lane >> 3) & 1) * 8;

    const int row = tid >> 1, seg = (tid & 1) * 32;
    const __half* gA = A + (size_t)(bm + row) * D_ + seg;
    const __half* gB = W + (size_t)(bn + row) * D_ + seg;
    const uint32_t uA = sbase + (uint32_t)(row*72 + seg) * 2;
    const uint32_t uB = uA + GS_A;

    float c[4][4][4] = {};

    // prologue: chunk 0 -> stage 0
    #pragma unroll
    for (int j = 0; j < 4; j++) {
        CP16(uA + j*16, gA + j*8);
        CP16(uB + j*16, gB + j*8);
    }
    CP_COMMIT();

    const int NCH = D_ / 64;   // 16
    for (int itb = 0; itb < NCH; itb += 2) {
        #pragma unroll
        for (int jj = 0; jj < 2; jj++) {
            const int it = itb + jj;
            CP_WAIT0();
            __syncthreads();
            // prefetch chunk it+1 into the other stage (safe: consumed in it-1)
            const int nxt = jj ^ 1;
            if (it + 1 < NCH) {
                #pragma unroll
                for (int j = 0; j < 4; j++) {
                    CP16(uA + nxt*GS_STG + j*16, gA + (it+1)*64 + j*8);
                    CP16(uB + nxt*GS_STG + j*16, gB + (it+1)*64 + j*8);
                }
            }
            CP_COMMIT();

            const uint32_t stA = sbase + jj*GS_STG;   // compile-time jj
            const uint32_t stB = stA + GS_A;
            #pragma unroll
            for (int kt = 0; kt < 4; kt++) {
                uint32_t a[4][4], b[4][2];
                #pragma unroll
                for (int mt = 0; mt < 4; mt++) {
                    uint32_t ad = stA + (uint32_t)((wm + mt*16 + aRow)*72 + kt*16 + aK) * 2;
                    LDSM4(a[mt][0], a[mt][1], a[mt][2], a[mt][3], ad);
                }
                #pragma unroll
                for (int p = 0; p < 2; p++) {
                    uint32_t ad = stB + (uint32_t)((wn + p*16 + bN)*72 + kt*16 + bK) * 2;
                    LDSM4(b[2*p][0], b[2*p][1], b[2*p+1][0], b[2*p+1][1], ad);
                }
                #pragma unroll
                for (int mt = 0; mt < 4; mt++)
                    #pragma unroll
                    for (int nt = 0; nt < 4; nt++)
                        mma16(c[mt][nt], a[mt][0], a[mt][1], a[mt][2], a[mt][3],
                              b[nt][0], b[nt][1]);
            }
        }
    }

    #pragma unroll
    for (int mt = 0; mt < 4; mt++) {
        #pragma unroll
        for (int p = 0; p < 2; p++) {
            int m = bm + wm + mt*16 + g + p*8;
            #pragma unroll
            for (int nt = 0; nt < 4; nt++) {
                int col = bn + wn + nt*8 + tig*2;
                float vx = c[mt][nt][p*2+0] + bias[col];
                float vy = c[mt][nt][p*2+1] + bias[col+1];
                if (mode == 0) {
                    float2 v; v.x = vx; v.y = vy;
                    *(float2*)&((float*)out)[(size_t)m * D_ + col] = v;
                } else if (mode == 1) {
                    int b_ = m >> 11, s = m & 2047;
                    int hh = col >> 6, e = col & 63;
                    __half2 hv = __floats2half2_rn(vx * oscale, vy * oscale);
                    *(__half2*)&((__half*)out)[(((size_t)(b_*H_ + hh)*S_ + s))*HD_ + e] = hv;
                } else {
                    int b_ = m >> 11, s = m & 2047;
                    int hh = col >> 6, e = col & 63;
                    __half* dst = (__half*)out + ((size_t)(b_*H_ + hh)*HD_)*S_;
                    dst[(size_t)(e  )*S_ + s] = __float2half_rn(vx);
                    dst[(size_t)(e+1)*S_ + s] = __float2half_rn(vy);
                }
            }
        }
    }
}

__global__ void __launch_bounds__(256, 2) proj_qkv(
    const float* __restrict__ bq, const float* __restrict__ bk, const float* __restrict__ bv)
{
    extern __shared__ char smc[];
    const __half *A, *W; const float* bias; void* out; float sc; int mode;
    if (blockIdx.z == 0)      { A = g_inq; W = g_wq; bias = bq; out = g_qh;
                                sc = 0.125f * 1.4426950408889634f; mode = 1; }
    else if (blockIdx.z == 1) { A = g_ink; W = g_wk; bias = bk; out = g_kh; sc = 1.0f; mode = 1; }
    else                      { A = g_inv; W = g_wv; bias = bv; out = g_vt; sc = 1.0f; mode = 2; }
    gemm_h_body(A, W, bias, out, mode, sc, blockIdx.y*128, blockIdx.x*128, smc);
}

__global__ void __launch_bounds__(256, 2) out_proj(
    const float* __restrict__ bias, float* __restrict__ out)
{
    extern __shared__ char smc[];
    gemm_h_body(g_atth, g_wo, bias, out, 0, 1.0f, blockIdx.y*128, blockIdx.x*128, smc);
}

// ---------------------------------------------------------------------------
// fp16 flash attention: 4-stage KV ring, loop unrolled x4 (compile-time stage),
// prefetch distance 3 (wait_group 2), skip-rescale when max unchanged.
// smem: Qs 128x72 h (18432) + 4 stages of (K 64x72 + V 64x72) (18432 each).
// ---------------------------------------------------------------------------
#define KV_STG   18432
#define ATTN_SMEM (18432 + 4*KV_STG)   // 92160
#define NITER (S_/64)

__global__ void __launch_bounds__(256, 2) attn_h()
{
    extern __shared__ char smc[];
    const int bh = blockIdx.y;
    const int b  = bh >> 4, h = bh & 15;
    const int q0 = blockIdx.x * 128;
    const __half* qp  = g_qh + (size_t)bh * S_ * HD_;
    const __half* kp  = g_kh + (size_t)bh * S_ * HD_;
    const __half* vtp = g_vt + (size_t)bh * HD_ * S_;

    const int tid = threadIdx.x;
    const int wid = tid >> 5, lane = tid & 31;
    const int g = lane >> 2, tig = lane & 3;
    const int wrow = wid * 16;
    const uint32_t sbase = smem_u32(smc);

    const int aRow = ((lane >> 3) & 1) * 8 + (lane & 7);
    const int aK   = (lane >> 4) * 8;
    const int bN   = (lane >> 4) * 8 + (lane & 7);
    const int bK   = ((lane >> 3) & 1) * 8;

    // Q: 128 rows x 64 halves
    {
        int row = tid >> 1, seg = (tid & 1) * 32;
        uint32_t dst = sbase + (uint32_t)(row*72 + seg) * 2;
        const __half* src = qp + (size_t)(q0 + row) * HD_ + seg;
        #pragma unroll
        for (int j = 0; j < 4; j++) CP16(dst + j*16, src + j*8);
    }
    const int kvr = tid >> 2, kvs = (tid & 3) * 16;
    const uint32_t ukb = sbase + 18432 + (uint32_t)(kvr*72 + kvs) * 2;
    const uint32_t uvb = ukb + 9216;
    // prologue: chunks 0,1,2 -> stages 0,1,2
    #pragma unroll
    for (int st = 0; st < 3; st++) {
        const __half* sk = kp  + (size_t)(st*64 + kvr) * HD_ + kvs;
        const __half* sv = vtp + (size_t)kvr * S_ + st*64 + kvs;
        CP16(ukb + st*KV_STG,      sk);
        CP16(ukb + st*KV_STG + 16, sk + 8);
        CP16(uvb + st*KV_STG,      sv);
        CP16(uvb + st*KV_STG + 16, sv + 8);
        CP_COMMIT();
    }

    float mx0 = -1e30f, mx1 = -1e30f;
    float acc[8][4] = {};
    float lacc[4] = {};   // row sums via ones-mma

    for (int itb = 0; itb < NITER; itb += 4) {
        #pragma unroll
        for (int jj = 0; jj < 4; jj++) {
            const int it = itb + jj;
            CP_WAIT2();
            __syncthreads();
            // prefetch chunk it+3 into stage (jj+3)&3 (consumed in it-1, safe)
            const int pf = (jj + 3) & 3;
            if (it + 3 < NITER) {
                const __half* sk = kp  + (size_t)((it+3)*64 + kvr) * HD_ + kvs;
                const __half* sv = vtp + (size_t)kvr * S_ + (it+3)*64 + kvs;
                CP16(ukb + pf*KV_STG,      sk);
                CP16(ukb + pf*KV_STG + 16, sk + 8);
                CP16(uvb + pf*KV_STG,      sv);
                CP16(uvb + pf*KV_STG + 16, sv + 8);
            }
            CP_COMMIT();

            const uint32_t stK = sbase + 18432 + jj*KV_STG;   // compile-time jj
            const uint32_t stV = stK + 9216;
            const uint32_t stQ = sbase;

            // S (log2 domain) = Q K^T : warp tile 16 x 64
            float s[8][4] = {};
            #pragma unroll
            for (int kt = 0; kt < 4; kt++) {
                uint32_t a0, a1, a2, a3;
                LDSM4(a0, a1, a2, a3,
                      stQ + (uint32_t)((wrow + aRow)*72 + kt*16 + aK) * 2);
                uint32_t bb[8][2];
                #pragma unroll
                for (int p = 0; p < 4; p++) {
                    uint32_t ad = stK + (uint32_t)((p*16 + bN)*72 + kt*16 + bK) * 2;
                    LDSM4(bb[2*p][0], bb[2*p][1], bb[2*p+1][0], bb[2*p+1][1], ad);
                }
                #pragma unroll
                for (int nt = 0; nt < 8; nt++)
                    mma16(s[nt], a0, a1, a2, a3, bb[nt][0], bb[nt][1]);
            }

            // online max
            float rm0 = -1e30f, rm1 = -1e30f;
            #pragma unroll
            for (int nt = 0; nt < 8; nt++) {
                rm0 = fmaxf(rm0, fmaxf(s[nt][0], s[nt][1]));
                rm1 = fmaxf(rm1, fmaxf(s[nt][2], s[nt][3]));
            }
            rm0 = fmaxf(rm0, __shfl_xor_sync(0xffffffffu, rm0, 1));
            rm0 = fmaxf(rm0, __shfl_xor_sync(0xffffffffu, rm0, 2));
            rm1 = fmaxf(rm1, __shfl_xor_sync(0xffffffffu, rm1, 1));
            rm1 = fmaxf(rm1, __shfl_xor_sync(0xffffffffu, rm1, 2));

            float nm0 = fmaxf(mx0, rm0), nm1 = fmaxf(mx1, rm1);
            // Rescale only if some lane's max moved (alpha==1 elsewhere -> identity)
            bool need = (nm0 > mx0) || (nm1 > mx1);
            if (__any_sync(0xffffffffu, need)) {
                float al0 = exp2f(mx0 - nm0), al1 = exp2f(mx1 - nm1);
                #pragma unroll
                for (int nt = 0; nt < 8; nt++) {
                    acc[nt][0] *= al0; acc[nt][1] *= al0;
                    acc[nt][2] *= al1; acc[nt][3] *= al1;
                }
                lacc[0] *= al0; lacc[1] *= al0; lacc[2] *= al1; lacc[3] *= al1;
            }
            mx0 = nm0; mx1 = nm1;

            // P = exp2(s - nm) pairwise in half2 (A-frag layout)
            uint32_t ph[8][2];
            #pragma unroll
            for (int nt = 0; nt < 8; nt++) {
                ph[nt][0] = ex2_h2(h2pack(s[nt][0] - nm0, s[nt][1] - nm0));
                ph[nt][1] = ex2_h2(h2pack(s[nt][2] - nm1, s[nt][3] - nm1));
            }

            // acc += P * V ; lacc += P * ones
            #pragma unroll
            for (int kt = 0; kt < 4; kt++) {
                uint32_t pa0 = ph[2*kt  ][0];
                uint32_t pa1 = ph[2*kt  ][1];
                uint32_t pa2 = ph[2*kt+1][0];
                uint32_t pa3 = ph[2*kt+1][1];
                uint32_t bb[8][2];
                #pragma unroll
                for (int p = 0; p < 4; p++) {
                    uint32_t ad = stV + (uint32_t)((p*16 + bN)*72 + kt*16 + bK) * 2;
                    LDSM4(bb[2*p][0], bb[2*p][1], bb[2*p+1][0], bb[2*p+1][1], ad);
                }
                #pragma unroll
                for (int nt = 0; nt < 8; nt++)
                    mma16(acc[nt], pa0, pa1, pa2, pa3, bb[nt][0], bb[nt][1]);
                mma16(lacc, pa0, pa1, pa2, pa3, ONES_H2, ONES_H2);
            }
        }
    }

    // epilogue: normalize, store half concat layout
    float inv0 = 1.0f / lacc[0], inv1 = 1.0f / lacc[2];
    int r0 = q0 + wrow + g;
    int r1 = r0 + 8;
    #pragma unroll
    for (int nt = 0; nt < 8; nt++) {
        int col = h*64 + nt*8 + tig*2;
        *(__half2*)&g_atth[(size_t)(b*S_ + r0)*D_ + col] =
            __floats2half2_rn(acc[nt][0]*inv0, acc[nt][1]*inv0);
        *(__half2*)&g_atth[(size_t)(b*S_ + r1)*D_ + col] =
            __floats2half2_rn(acc[nt][2]*inv1, acc[nt][3]*inv1);
    }
}

// ---------------------------------------------------------------------------
extern "C" void kernel_launch(void* const* d_in, const int* in_sizes, int n_in,
                              void* d_out, int out_size)
{
    const float* V  = (const float*)d_in[0];
    const float* K  = (const float*)d_in[1];
    const float* Q  = (const float*)d_in[2];
    const float* Wv = (const float*)d_in[3];
    const float* bv = (const float*)d_in[4];
    const float* Wk = (const float*)d_in[5];
    const float* bk = (const float*)d_in[6];
    const float* Wq = (const float*)d_in[7];
    const float* bq = (const float*)d_in[8];
    const float* Wo = (const float*)d_in[9];
    const float* bo = (const float*)d_in[10];
    float* out = (float*)d_out;

    (void)in_sizes; (void)n_in; (void)out_size;

    dim3 gact(MROWS*D_/8/256, 3);
    cvt_act<<<gact, 256>>>(Q, K, V);
    dim3 gwt(D_*D_/8/256, 4);
    cvt_wt<<<gwt, 256>>>(Wq, Wk, Wv, Wo);

    cudaFuncSetAttribute(proj_qkv, cudaFuncAttributeMaxDynamicSharedMemorySize, GEMM_SMEM);
    cudaFuncSetAttribute(out_proj, cudaFuncAttributeMaxDynamicSharedMemorySize, GEMM_SMEM);
    cudaFuncSetAttribute(attn_h,   cudaFuncAttributeMaxDynamicSharedMemorySize, ATTN_SMEM);

    dim3 gproj(D_/128, MROWS/128, 3);
    proj_qkv<<<gproj, 256, GEMM_SMEM>>>(bq, bk, bv);

    dim3 ga_grid(S_/128, B_*H_);
    attn_h<<<ga_grid, 256, ATTN_SMEM>>>();

    dim3 gout(D_/128, MROWS/128);
    out_proj<<<gout, 256, GEMM_SMEM>>>(bo, out);
}